// round 11
// baseline (speedup 1.0000x reference)
#include <cuda_runtime.h>
#include <cuda_fp16.h>
#include <cstdint>

#define N_NODES 50000
#define N_EDGES 800000
#define D 64
#define N_GRAPHS 512
#define N_LAYERS 3
#define HID_FC 64
#define N_CLASSES 10
#define PAD_A 68   // smem row stride for A tiles: banks 4g+th -> conflict-free
#define PAD_B 72   // smem row stride for W tiles: banks 8th+g -> conflict-free
#define CAP 128    // adjacency bucket capacity per node (mean deg = 16)
#define MROWS 128  // rows per layer block

// dynamic smem (floats): As[128*68] | Ws1[64*72] | Ws2[64*72] | b1s[64] | b2s[64]
#define SMEM_FLOATS (MROWS * PAD_A + 2 * D * PAD_B + 2 * D)

// Scratch (device globals: no allocations allowed)
__device__ __half g_xh[N_NODES * D];              // input x, fp16
__device__ __half g_hA[N_NODES * D];              // layer ping
__device__ __half g_hB[N_NODES * D];              // layer pong
__device__ unsigned int g_pool[N_GRAPHS * D];
__device__ int g_cur[N_NODES];
__device__ int g_adj[N_NODES * CAP];
__device__ unsigned int g_w1t[N_LAYERS * D * D];  // tf32-converted weights
__device__ unsigned int g_w2t[N_LAYERS * D * D];

// ---------------------------------------------------------------------------
__device__ __forceinline__ uint32_t f2tf(float f) {
    uint32_t u;
    asm("cvt.rna.tf32.f32 %0, %1;" : "=r"(u) : "f"(f));
    return u;
}

__device__ __forceinline__ float4 h4_to_f4(uint2 u) {
    float2 f0 = __half22float2(*reinterpret_cast<const __half2*>(&u.x));
    float2 f1 = __half22float2(*reinterpret_cast<const __half2*>(&u.y));
    return make_float4(f0.x, f0.y, f1.x, f1.y);
}

// ---------------------------------------------------------------------------
// Prep (once per replay): weights -> tf32, pool init, x -> fp16
// ---------------------------------------------------------------------------
__global__ void prep_kernel(const float* __restrict__ x,
                            const float* __restrict__ convW1,
                            const float* __restrict__ convW2) {
    int i = blockIdx.x * blockDim.x + threadIdx.x;
    if (i < N_LAYERS * D * D) {
        g_w1t[i] = f2tf(convW1[i]);
        g_w2t[i] = f2tf(convW2[i]);
    }
    if (i < N_GRAPHS * D) g_pool[i] = 0x00800000u;  // encode(-FLT_MAX)
    if (i < N_NODES * D / 2) {
        float2 v = reinterpret_cast<const float2*>(x)[i];
        reinterpret_cast<__half2*>(g_xh)[i] = __floats2half2_rn(v.x, v.y);
    }
}

// ---------------------------------------------------------------------------
// Bucket fill: g_adj[d*CAP + pos] = s for each edge (s -> d). 8 edges/thread.
// ---------------------------------------------------------------------------
__global__ void fill_kernel(const int* __restrict__ src, const int* __restrict__ dst) {
    int e = (blockIdx.x * blockDim.x + threadIdx.x) * 8;
    if (e >= N_EDGES) return;  // N_EDGES % 8 == 0
    int4 d0 = *reinterpret_cast<const int4*>(dst + e);
    int4 d1 = *reinterpret_cast<const int4*>(dst + e + 4);
    int4 s0 = *reinterpret_cast<const int4*>(src + e);
    int4 s1 = *reinterpret_cast<const int4*>(src + e + 4);
    int p0 = atomicAdd(&g_cur[d0.x], 1);
    int p1 = atomicAdd(&g_cur[d0.y], 1);
    int p2 = atomicAdd(&g_cur[d0.z], 1);
    int p3 = atomicAdd(&g_cur[d0.w], 1);
    int p4 = atomicAdd(&g_cur[d1.x], 1);
    int p5 = atomicAdd(&g_cur[d1.y], 1);
    int p6 = atomicAdd(&g_cur[d1.z], 1);
    int p7 = atomicAdd(&g_cur[d1.w], 1);
    g_adj[d0.x * CAP + p0] = s0.x;
    g_adj[d0.y * CAP + p1] = s0.y;
    g_adj[d0.z * CAP + p2] = s0.z;
    g_adj[d0.w * CAP + p3] = s0.w;
    g_adj[d1.x * CAP + p4] = s1.x;
    g_adj[d1.y * CAP + p5] = s1.y;
    g_adj[d1.z * CAP + p6] = s1.z;
    g_adj[d1.w * CAP + p7] = s1.w;
}

// ---------------------------------------------------------------------------
// Fused GIN layer: gather (into As, tf32) + MLP (tensor cores) in one kernel.
// Block = 256 threads = 128 rows. Gather: 16 lanes/node, 8 nodes per group,
// reading fp16 rows of hin; accumulate fp32; emit tf32 into As.
// Then: h_out = relu(agg @ W1 + b1) @ W2 + b2 via m16n8k8 tf32 MMA; GEMM2
// A-fragments come from GEMM1 accumulators via shfl (no smem round-trip).
// mode 0: write hout (fp16, OTHER buffer than hin); mode 1: fused max-pool.
// ---------------------------------------------------------------------------
__device__ __forceinline__ void mma_tf32(float* c, uint32_t a0, uint32_t a1,
                                         uint32_t a2, uint32_t a3,
                                         uint32_t b0, uint32_t b1) {
    asm volatile(
        "mma.sync.aligned.m16n8k8.row.col.f32.tf32.tf32.f32 "
        "{%0,%1,%2,%3}, {%4,%5,%6,%7}, {%8,%9}, {%0,%1,%2,%3};"
        : "+f"(c[0]), "+f"(c[1]), "+f"(c[2]), "+f"(c[3])
        : "r"(a0), "r"(a1), "r"(a2), "r"(a3), "r"(b0), "r"(b1));
}

__global__ __launch_bounds__(256, 3) void layer_kernel(const uint2* __restrict__ hin2,
                                                       const unsigned int* __restrict__ W1t,
                                                       const float* __restrict__ b1,
                                                       const unsigned int* __restrict__ W2t,
                                                       const float* __restrict__ b2,
                                                       __half* __restrict__ hout,
                                                       const int* __restrict__ batch,
                                                       int mode) {
    extern __shared__ float smem[];
    float* As  = smem;                        // MROWS * PAD_A
    float* Ws1 = As + MROWS * PAD_A;          // D * PAD_B
    float* Ws2 = Ws1 + D * PAD_B;             // D * PAD_B
    float* b1s = Ws2 + D * PAD_B;             // D
    float* b2s = b1s + D;                     // D

    int tid = threadIdx.x;
    int warp = tid >> 5;
    int lane = tid & 31;
    int g = lane >> 2;   // group 0..7 (mma row)
    int th = lane & 3;   // thread-in-group 0..3
    int arow = warp * 16;
    int row0 = blockIdx.x * MROWS;

    // ---- stage W1 + W2 + biases ----
    for (int i = tid; i < D * 16; i += 256) {
        int r = i >> 4;
        int c4 = (i & 15) << 2;
        uint4 t1 = reinterpret_cast<const uint4*>(W1t)[i];
        uint4 t2 = reinterpret_cast<const uint4*>(W2t)[i];
        *reinterpret_cast<uint4*>(&Ws1[r * PAD_B + c4]) = t1;
        *reinterpret_cast<uint4*>(&Ws2[r * PAD_B + c4]) = t2;
    }
    if (tid < D) { b1s[tid] = b1[tid]; b2s[tid] = b2[tid]; }

    // ---- gather phase: agg rows -> As (tf32) ----
    {
        int grp = tid >> 4;        // 0..15
        int ln = tid & 15;         // 0..15
        unsigned int hm = 0xFFFFu << (tid & 16);  // this 16-lane segment

        for (int sub = 0; sub < 8; sub++) {
            int r = grp * 8 + sub;           // 0..127
            int node = row0 + r;
            float4 a0 = make_float4(0.f, 0.f, 0.f, 0.f);
            if (node < N_NODES) {
                a0 = h4_to_f4(hin2[(size_t)node * 16 + ln]);  // self (eps=0)
                float4 a1 = make_float4(0.f, 0.f, 0.f, 0.f);
                int cnt = g_cur[node];
                const int* adj = g_adj + (size_t)node * CAP;
                for (int base = 0; base < cnt; base += 16) {
                    int my = base + ln;
                    int idx = (my < cnt) ? __ldg(adj + my) : 0;
                    int m = cnt - base;
                    if (m >= 16) {
#pragma unroll
                        for (int j = 0; j < 16; j += 4) {
                            int n0 = __shfl_sync(hm, idx, j + 0, 16);
                            int n1 = __shfl_sync(hm, idx, j + 1, 16);
                            int n2 = __shfl_sync(hm, idx, j + 2, 16);
                            int n3 = __shfl_sync(hm, idx, j + 3, 16);
                            float4 v0 = h4_to_f4(hin2[(size_t)n0 * 16 + ln]);
                            float4 v1 = h4_to_f4(hin2[(size_t)n1 * 16 + ln]);
                            float4 v2 = h4_to_f4(hin2[(size_t)n2 * 16 + ln]);
                            float4 v3 = h4_to_f4(hin2[(size_t)n3 * 16 + ln]);
                            a0.x += v0.x; a0.y += v0.y; a0.z += v0.z; a0.w += v0.w;
                            a1.x += v1.x; a1.y += v1.y; a1.z += v1.z; a1.w += v1.w;
                            a0.x += v2.x; a0.y += v2.y; a0.z += v2.z; a0.w += v2.w;
                            a1.x += v3.x; a1.y += v3.y; a1.z += v3.z; a1.w += v3.w;
                        }
                    } else {
                        for (int j = 0; j < m; j++) {
                            int nb = __shfl_sync(hm, idx, j, 16);
                            float4 v = h4_to_f4(hin2[(size_t)nb * 16 + ln]);
                            a0.x += v.x; a0.y += v.y; a0.z += v.z; a0.w += v.w;
                        }
                    }
                }
                a0.x += a1.x; a0.y += a1.y; a0.z += a1.z; a0.w += a1.w;
            }
            uint4 o;
            o.x = f2tf(a0.x); o.y = f2tf(a0.y); o.z = f2tf(a0.z); o.w = f2tf(a0.w);
            *reinterpret_cast<uint4*>(&As[r * PAD_A + (ln << 2)]) = o;
        }
    }
    __syncthreads();

    // ---- GEMM 1: acc = A @ W1 ----
    float acc[8][4];
#pragma unroll
    for (int n = 0; n < 8; n++)
#pragma unroll
        for (int j = 0; j < 4; j++) acc[n][j] = 0.f;

#pragma unroll
    for (int k = 0; k < 8; k++) {
        uint32_t a0 = __float_as_uint(As[(arow + g) * PAD_A + k * 8 + th]);
        uint32_t a1 = __float_as_uint(As[(arow + g + 8) * PAD_A + k * 8 + th]);
        uint32_t a2 = __float_as_uint(As[(arow + g) * PAD_A + k * 8 + th + 4]);
        uint32_t a3 = __float_as_uint(As[(arow + g + 8) * PAD_A + k * 8 + th + 4]);
#pragma unroll
        for (int n = 0; n < 8; n++) {
            uint32_t bf0 = __float_as_uint(Ws1[(k * 8 + th) * PAD_B + n * 8 + g]);
            uint32_t bf1 = __float_as_uint(Ws1[(k * 8 + th + 4) * PAD_B + n * 8 + g]);
            mma_tf32(acc[n], a0, a1, a2, a3, bf0, bf1);
        }
    }

    // ---- bias + relu (acc becomes T) ----
#pragma unroll
    for (int n = 0; n < 8; n++) {
        int c = n * 8 + 2 * th;
        acc[n][0] = fmaxf(acc[n][0] + b1s[c], 0.f);
        acc[n][1] = fmaxf(acc[n][1] + b1s[c + 1], 0.f);
        acc[n][2] = fmaxf(acc[n][2] + b1s[c], 0.f);
        acc[n][3] = fmaxf(acc[n][3] + b1s[c + 1], 0.f);
    }

    // ---- GEMM 2: acc2 = T @ W2; A-fragments from acc via intra-group shfl ----
    float acc2[8][4];
#pragma unroll
    for (int n = 0; n < 8; n++)
#pragma unroll
        for (int j = 0; j < 4; j++) acc2[n][j] = 0.f;

    int srcA = (lane & ~3) | (th >> 1);  // holds T cols k*8 + th
    int srcB = srcA + 2;                 // holds T cols k*8 + th + 4
    bool odd = (th & 1);

#pragma unroll
    for (int k = 0; k < 8; k++) {
        float t0A = __shfl_sync(0xffffffffu, acc[k][0], srcA);
        float t1A = __shfl_sync(0xffffffffu, acc[k][1], srcA);
        float t2A = __shfl_sync(0xffffffffu, acc[k][2], srcA);
        float t3A = __shfl_sync(0xffffffffu, acc[k][3], srcA);
        float t0B = __shfl_sync(0xffffffffu, acc[k][0], srcB);
        float t1B = __shfl_sync(0xffffffffu, acc[k][1], srcB);
        float t2B = __shfl_sync(0xffffffffu, acc[k][2], srcB);
        float t3B = __shfl_sync(0xffffffffu, acc[k][3], srcB);
        uint32_t a0 = f2tf(odd ? t1A : t0A);
        uint32_t a1 = f2tf(odd ? t3A : t2A);
        uint32_t a2 = f2tf(odd ? t1B : t0B);
        uint32_t a3 = f2tf(odd ? t3B : t2B);
#pragma unroll
        for (int n = 0; n < 8; n++) {
            uint32_t bf0 = __float_as_uint(Ws2[(k * 8 + th) * PAD_B + n * 8 + g]);
            uint32_t bf1 = __float_as_uint(Ws2[(k * 8 + th + 4) * PAD_B + n * 8 + g]);
            mma_tf32(acc2[n], a0, a1, a2, a3, bf0, bf1);
        }
    }

    // ---- bias + output ----
    int r0 = row0 + arow + g;
    int r1 = r0 + 8;
    bool v0 = (r0 < N_NODES);
    bool v1 = (r1 < N_NODES);

    if (mode == 0) {
#pragma unroll
        for (int n = 0; n < 8; n++) {
            int c = n * 8 + 2 * th;
            if (v0) {
                __half2 o = __floats2half2_rn(acc2[n][0] + b2s[c], acc2[n][1] + b2s[c + 1]);
                *reinterpret_cast<__half2*>(&hout[(size_t)r0 * D + c]) = o;
            }
            if (v1) {
                __half2 o = __floats2half2_rn(acc2[n][2] + b2s[c], acc2[n][3] + b2s[c + 1]);
                *reinterpret_cast<__half2*>(&hout[(size_t)r1 * D + c]) = o;
            }
        }
    } else {
        int gb0 = v0 ? batch[r0] : 0;
        int gb1 = v1 ? batch[r1] : 0;
        unsigned int* p0 = g_pool + (size_t)gb0 * D;
        unsigned int* p1 = g_pool + (size_t)gb1 * D;
#pragma unroll
        for (int n = 0; n < 8; n++) {
            int c = n * 8 + 2 * th;
#pragma unroll
            for (int j = 0; j < 4; j++) {
                float val = acc2[n][j] + b2s[c + (j & 1)];
                unsigned int bits = __float_as_uint(val);
                unsigned int enc = (bits & 0x80000000u) ? ~bits : (bits | 0x80000000u);
                if (j < 2) { if (v0) atomicMax(&p0[c + (j & 1)], enc); }
                else       { if (v1) atomicMax(&p1[c + (j & 1)], enc); }
            }
        }
    }
}

// ---------------------------------------------------------------------------
// FC head + log_softmax. One block (64 threads) per graph.
// ---------------------------------------------------------------------------
__global__ __launch_bounds__(64) void fc_kernel(const float* __restrict__ fcW1,
                                                const float* __restrict__ fcb1,
                                                const float* __restrict__ fcW2,
                                                const float* __restrict__ fcb2,
                                                float* __restrict__ out) {
    __shared__ float xr[D];
    __shared__ float hid[HID_FC];
    __shared__ float logits[N_CLASSES];
    __shared__ float m_s, lse_s;

    int g = blockIdx.x;
    int t = threadIdx.x;

    unsigned int e = g_pool[(size_t)g * D + t];
    unsigned int u = (e & 0x80000000u) ? (e & 0x7FFFFFFFu) : ~e;
    xr[t] = __uint_as_float(u);
    __syncthreads();

    float a = fcb1[t];
#pragma unroll
    for (int k = 0; k < D; k++) a += xr[k] * fcW1[k * HID_FC + t];
    hid[t] = fmaxf(a, 0.0f);
    __syncthreads();

    if (t < N_CLASSES) {
        float a2 = fcb2[t];
#pragma unroll
        for (int k = 0; k < HID_FC; k++) a2 += hid[k] * fcW2[k * N_CLASSES + t];
        logits[t] = a2;
    }
    __syncthreads();

    if (t == 0) {
        float m = logits[0];
#pragma unroll
        for (int j = 1; j < N_CLASSES; j++) m = fmaxf(m, logits[j]);
        float s = 0.0f;
#pragma unroll
        for (int j = 0; j < N_CLASSES; j++) s += expf(logits[j] - m);
        m_s = m;
        lse_s = logf(s);
    }
    __syncthreads();

    if (t < N_CLASSES) out[(size_t)g * N_CLASSES + t] = logits[t] - m_s - lse_s;
}

// ---------------------------------------------------------------------------
extern "C" void kernel_launch(void* const* d_in, const int* in_sizes, int n_in,
                              void* d_out, int out_size) {
    const float* x      = (const float*)d_in[0];
    const float* convW1 = (const float*)d_in[1];
    const float* convb1 = (const float*)d_in[2];
    const float* convW2 = (const float*)d_in[3];
    const float* convb2 = (const float*)d_in[4];
    const float* fcW1   = (const float*)d_in[5];
    const float* fcb1   = (const float*)d_in[6];
    const float* fcW2   = (const float*)d_in[7];
    const float* fcb2   = (const float*)d_in[8];
    const int* edge_index = (const int*)d_in[9];
    const int* batch      = (const int*)d_in[10];
    float* out = (float*)d_out;

    const int* src = edge_index;
    const int* dst = edge_index + N_EDGES;

    __half* xh_ptr = nullptr;
    __half* hA_ptr = nullptr;
    __half* hB_ptr = nullptr;
    int* cur_ptr = nullptr;
    unsigned int* w1t_ptr = nullptr;
    unsigned int* w2t_ptr = nullptr;
    cudaGetSymbolAddress((void**)&xh_ptr, g_xh);
    cudaGetSymbolAddress((void**)&hA_ptr, g_hA);
    cudaGetSymbolAddress((void**)&hB_ptr, g_hB);
    cudaGetSymbolAddress((void**)&cur_ptr, g_cur);
    cudaGetSymbolAddress((void**)&w1t_ptr, g_w1t);
    cudaGetSymbolAddress((void**)&w2t_ptr, g_w2t);

    const size_t layer_smem = SMEM_FLOATS * sizeof(float);  // 72192 bytes
    cudaFuncSetAttribute(layer_kernel,
                         cudaFuncAttributeMaxDynamicSharedMemorySize,
                         (int)layer_smem);

    const int e8_blocks = (N_EDGES / 8 + 255) / 256;         // 391
    const int layer_blocks = (N_NODES + MROWS - 1) / MROWS;  // 391
    const int prep_blocks = (N_NODES * D / 2 + 255) / 256;   // covers all prep jobs

    // ---- per-replay setup ----
    cudaMemsetAsync(cur_ptr, 0, (size_t)N_NODES * sizeof(int));
    prep_kernel<<<prep_blocks, 256>>>(x, convW1, convW2);
    fill_kernel<<<e8_blocks, 256>>>(src, dst);

    // ---- 3 fused GIN layers (double-buffered h: xh -> hA -> hB -> pool) ----
    const __half* ins[N_LAYERS]  = {xh_ptr, hA_ptr, hB_ptr};
    __half* outs[N_LAYERS]       = {hA_ptr, hB_ptr, hA_ptr};  // last unused
    for (int l = 0; l < N_LAYERS; l++) {
        int mode = (l == N_LAYERS - 1) ? 1 : 0;
        layer_kernel<<<layer_blocks, 256, layer_smem>>>((const uint2*)ins[l],
                                           w1t_ptr + (size_t)l * D * D, convb1 + (size_t)l * D,
                                           w2t_ptr + (size_t)l * D * D, convb2 + (size_t)l * D,
                                           outs[l], batch, mode);
    }

    fc_kernel<<<N_GRAPHS, 64>>>(fcW1, fcb1, fcW2, fcb2, out);
}

// round 12
// speedup vs baseline: 1.2392x; 1.2392x over previous
#include <cuda_runtime.h>
#include <cuda_fp16.h>
#include <cstdint>

#define N_NODES 50000
#define N_EDGES 800000
#define D 64
#define N_GRAPHS 512
#define N_LAYERS 3
#define HID_FC 64
#define N_CLASSES 10
#define SA 72      // smem stride in HALVES for A and W tiles: frag banks 4g+th
#define CAP 128    // adjacency bucket capacity per node (mean deg = 16)
#define MROWS 128  // rows per MLP block

// Scratch (device globals: no allocations allowed)
__device__ __half g_xh[N_NODES * D];     // input x, fp16
__device__ __half g_h[N_NODES * D];      // layer activations, fp16
__device__ __half g_aggh[N_NODES * D];   // aggregated rows, fp16
__device__ unsigned int g_pool[N_GRAPHS * D];
__device__ int g_cur[N_NODES];
__device__ int g_adj[N_NODES * CAP];
__device__ __half g_w1h[N_LAYERS * D * D];  // W1 fp16, TRANSPOSED: [out n][in k]
__device__ __half g_w2h[N_LAYERS * D * D];  // W2 fp16, TRANSPOSED: [out n][in k]

// ---------------------------------------------------------------------------
__device__ __forceinline__ float4 h4_to_f4(uint2 u) {
    float2 f0 = __half22float2(*reinterpret_cast<const __half2*>(&u.x));
    float2 f1 = __half22float2(*reinterpret_cast<const __half2*>(&u.y));
    return make_float4(f0.x, f0.y, f1.x, f1.y);
}

__device__ __forceinline__ uint32_t pack_h2(float lo, float hi) {
    __half2 h = __floats2half2_rn(lo, hi);
    return *reinterpret_cast<uint32_t*>(&h);
}

// ---------------------------------------------------------------------------
// Prep (once per replay): weights -> fp16 transposed, pool init, x -> fp16
// ---------------------------------------------------------------------------
__global__ void prep_kernel(const float* __restrict__ x,
                            const float* __restrict__ convW1,
                            const float* __restrict__ convW2) {
    int i = blockIdx.x * blockDim.x + threadIdx.x;
    if (i < N_LAYERS * D * D) {
        int l = i >> 12;
        int rem = i & 4095;
        int n = rem >> 6;   // output col
        int k = rem & 63;   // input row
        g_w1h[i] = __float2half(convW1[(l << 12) + (k << 6) + n]);
        g_w2h[i] = __float2half(convW2[(l << 12) + (k << 6) + n]);
    }
    if (i < N_GRAPHS * D) g_pool[i] = 0x00800000u;  // encode(-FLT_MAX)
    if (i < N_NODES * D / 2) {
        float2 v = reinterpret_cast<const float2*>(x)[i];
        reinterpret_cast<__half2*>(g_xh)[i] = __floats2half2_rn(v.x, v.y);
    }
}

// ---------------------------------------------------------------------------
// Bucket fill: g_adj[d*CAP + pos] = s for each edge (s -> d). 8 edges/thread.
// ---------------------------------------------------------------------------
__global__ void fill_kernel(const int* __restrict__ src, const int* __restrict__ dst) {
    int e = (blockIdx.x * blockDim.x + threadIdx.x) * 8;
    if (e >= N_EDGES) return;  // N_EDGES % 8 == 0
    int4 d0 = *reinterpret_cast<const int4*>(dst + e);
    int4 d1 = *reinterpret_cast<const int4*>(dst + e + 4);
    int4 s0 = *reinterpret_cast<const int4*>(src + e);
    int4 s1 = *reinterpret_cast<const int4*>(src + e + 4);
    int p0 = atomicAdd(&g_cur[d0.x], 1);
    int p1 = atomicAdd(&g_cur[d0.y], 1);
    int p2 = atomicAdd(&g_cur[d0.z], 1);
    int p3 = atomicAdd(&g_cur[d0.w], 1);
    int p4 = atomicAdd(&g_cur[d1.x], 1);
    int p5 = atomicAdd(&g_cur[d1.y], 1);
    int p6 = atomicAdd(&g_cur[d1.z], 1);
    int p7 = atomicAdd(&g_cur[d1.w], 1);
    g_adj[d0.x * CAP + p0] = s0.x;
    g_adj[d0.y * CAP + p1] = s0.y;
    g_adj[d0.z * CAP + p2] = s0.z;
    g_adj[d0.w * CAP + p3] = s0.w;
    g_adj[d1.x * CAP + p4] = s1.x;
    g_adj[d1.y * CAP + p5] = s1.y;
    g_adj[d1.z * CAP + p6] = s1.z;
    g_adj[d1.w * CAP + p7] = s1.w;
}

// ---------------------------------------------------------------------------
// Gather aggregation: aggh[n] = fp16(h[n] + sum_{j in N(n)} h[j]); h is fp16.
// 16 threads per node, 4 halves (8B) per lane; fp32 accumulation.
// ---------------------------------------------------------------------------
__global__ __launch_bounds__(256, 6) void gather_kernel(const uint2* __restrict__ hin2,
                                                        uint2* __restrict__ aggh2) {
    unsigned int gid = blockIdx.x * 256u + threadIdx.x;
    unsigned int node = gid >> 4;
    unsigned int lane = gid & 15u;
    if (node >= N_NODES) return;
    unsigned int hm = 0xFFFFu << (threadIdx.x & 16);  // this 16-lane segment

    float4 a0 = h4_to_f4(hin2[(size_t)node * 16 + lane]);  // self term (eps = 0)
    float4 a1 = make_float4(0.f, 0.f, 0.f, 0.f);

    int cnt = g_cur[node];
    const int* adj = g_adj + (size_t)node * CAP;

    for (int base = 0; base < cnt; base += 16) {
        int my = base + (int)lane;
        int idx = (my < cnt) ? __ldg(adj + my) : 0;
        int m = cnt - base;
        if (m >= 16) {
#pragma unroll
            for (int j = 0; j < 16; j += 4) {
                int n0 = __shfl_sync(hm, idx, j + 0, 16);
                int n1 = __shfl_sync(hm, idx, j + 1, 16);
                int n2 = __shfl_sync(hm, idx, j + 2, 16);
                int n3 = __shfl_sync(hm, idx, j + 3, 16);
                float4 v0 = h4_to_f4(hin2[(size_t)n0 * 16 + lane]);
                float4 v1 = h4_to_f4(hin2[(size_t)n1 * 16 + lane]);
                float4 v2 = h4_to_f4(hin2[(size_t)n2 * 16 + lane]);
                float4 v3 = h4_to_f4(hin2[(size_t)n3 * 16 + lane]);
                a0.x += v0.x; a0.y += v0.y; a0.z += v0.z; a0.w += v0.w;
                a1.x += v1.x; a1.y += v1.y; a1.z += v1.z; a1.w += v1.w;
                a0.x += v2.x; a0.y += v2.y; a0.z += v2.z; a0.w += v2.w;
                a1.x += v3.x; a1.y += v3.y; a1.z += v3.z; a1.w += v3.w;
            }
        } else {
            for (int j = 0; j < m; j++) {
                int nb = __shfl_sync(hm, idx, j, 16);
                float4 v = h4_to_f4(hin2[(size_t)nb * 16 + lane]);
                a0.x += v.x; a0.y += v.y; a0.z += v.z; a0.w += v.w;
            }
        }
    }
    a0.x += a1.x; a0.y += a1.y; a0.z += a1.z; a0.w += a1.w;

    uint2 o;
    o.x = pack_h2(a0.x, a0.y);
    o.y = pack_h2(a0.z, a0.w);
    aggh2[(size_t)node * 16 + lane] = o;
}

// ---------------------------------------------------------------------------
// FP16 tensor-core fused MLP: h_out = relu(agg @ W1 + b1) @ W2 + b2
// mma.sync m16n8k16 f16.f16.f32. Block = 256 threads = 128 rows.
// W stored transposed [n][k] so B-frags are k-contiguous half2 loads.
// GEMM2 A-fragments == GEMM1 C-fragments (same thread) -> just cvt+pack.
// mode 0: write hout (fp16); mode 1: fused global-max-pool into g_pool
// ---------------------------------------------------------------------------
__device__ __forceinline__ void mma_f16(float* c, uint32_t a0, uint32_t a1,
                                        uint32_t a2, uint32_t a3,
                                        uint32_t b0, uint32_t b1) {
    asm volatile(
        "mma.sync.aligned.m16n8k16.row.col.f32.f16.f16.f32 "
        "{%0,%1,%2,%3}, {%4,%5,%6,%7}, {%8,%9}, {%0,%1,%2,%3};"
        : "+f"(c[0]), "+f"(c[1]), "+f"(c[2]), "+f"(c[3])
        : "r"(a0), "r"(a1), "r"(a2), "r"(a3), "r"(b0), "r"(b1));
}

__global__ __launch_bounds__(256, 3) void mlp_tc_kernel(const uint4* __restrict__ xinh,
                                                        const __half* __restrict__ W1h,
                                                        const float* __restrict__ b1,
                                                        const __half* __restrict__ W2h,
                                                        const float* __restrict__ b2,
                                                        __half* __restrict__ hout,
                                                        const int* __restrict__ batch,
                                                        int mode) {
    __shared__ __half As[MROWS * SA];   // A tile (fp16)
    __shared__ __half Ws1[D * SA];      // W1^T (fp16)
    __shared__ __half Ws2[D * SA];      // W2^T (fp16)
    __shared__ float b1s[D];
    __shared__ float b2s[D];

    int tid = threadIdx.x;
    int warp = tid >> 5;
    int lane = tid & 31;
    int g = lane >> 2;   // group 0..7
    int th = lane & 3;   // thread-in-group 0..3
    int arow = warp * 16;
    int row0 = blockIdx.x * MROWS;

    // ---- stage A (128 rows x 8 uint4) + W1^T + W2^T (64 rows x 8 uint4 each) ----
    for (int i = tid; i < MROWS * 8; i += 256) {
        int r = i >> 3;
        int c8 = (i & 7) << 3;
        uint4 t = make_uint4(0u, 0u, 0u, 0u);
        if (row0 + r < N_NODES)
            t = xinh[(size_t)(row0 + r) * 8 + (i & 7)];
        *reinterpret_cast<uint4*>(&As[r * SA + c8]) = t;
    }
    for (int i = tid; i < D * 8; i += 256) {
        int n = i >> 3;
        int c8 = (i & 7) << 3;
        uint4 t1 = reinterpret_cast<const uint4*>(W1h)[i];
        uint4 t2 = reinterpret_cast<const uint4*>(W2h)[i];
        *reinterpret_cast<uint4*>(&Ws1[n * SA + c8]) = t1;
        *reinterpret_cast<uint4*>(&Ws2[n * SA + c8]) = t2;
    }
    if (tid < D) { b1s[tid] = b1[tid]; b2s[tid] = b2[tid]; }
    __syncthreads();

    // ---- GEMM 1: acc = A @ W1  (4 k-chunks of 16) ----
    float acc[8][4];
#pragma unroll
    for (int n = 0; n < 8; n++)
#pragma unroll
        for (int j = 0; j < 4; j++) acc[n][j] = 0.f;

#pragma unroll
    for (int kc = 0; kc < 4; kc++) {
        uint32_t a0 = *reinterpret_cast<const uint32_t*>(&As[(arow + g) * SA + kc * 16 + 2 * th]);
        uint32_t a1 = *reinterpret_cast<const uint32_t*>(&As[(arow + g + 8) * SA + kc * 16 + 2 * th]);
        uint32_t a2 = *reinterpret_cast<const uint32_t*>(&As[(arow + g) * SA + kc * 16 + 2 * th + 8]);
        uint32_t a3 = *reinterpret_cast<const uint32_t*>(&As[(arow + g + 8) * SA + kc * 16 + 2 * th + 8]);
#pragma unroll
        for (int n = 0; n < 8; n++) {
            uint32_t bf0 = *reinterpret_cast<const uint32_t*>(&Ws1[(n * 8 + g) * SA + kc * 16 + 2 * th]);
            uint32_t bf1 = *reinterpret_cast<const uint32_t*>(&Ws1[(n * 8 + g) * SA + kc * 16 + 2 * th + 8]);
            mma_f16(acc[n], a0, a1, a2, a3, bf0, bf1);
        }
    }

    // ---- bias + relu (acc becomes T, fp32) ----
#pragma unroll
    for (int n = 0; n < 8; n++) {
        int c = n * 8 + 2 * th;
        acc[n][0] = fmaxf(acc[n][0] + b1s[c], 0.f);
        acc[n][1] = fmaxf(acc[n][1] + b1s[c + 1], 0.f);
        acc[n][2] = fmaxf(acc[n][2] + b1s[c], 0.f);
        acc[n][3] = fmaxf(acc[n][3] + b1s[c + 1], 0.f);
    }

    // ---- GEMM 2: acc2 = T @ W2; A-frags = own C-frags, cvt+pack only ----
    float acc2[8][4];
#pragma unroll
    for (int n = 0; n < 8; n++)
#pragma unroll
        for (int j = 0; j < 4; j++) acc2[n][j] = 0.f;

#pragma unroll
    for (int kc = 0; kc < 4; kc++) {
        uint32_t a0 = pack_h2(acc[2 * kc][0], acc[2 * kc][1]);         // rows g,  cols 16kc+2th
        uint32_t a1 = pack_h2(acc[2 * kc][2], acc[2 * kc][3]);         // rows g+8
        uint32_t a2 = pack_h2(acc[2 * kc + 1][0], acc[2 * kc + 1][1]); // rows g,  cols +8
        uint32_t a3 = pack_h2(acc[2 * kc + 1][2], acc[2 * kc + 1][3]); // rows g+8
#pragma unroll
        for (int n = 0; n < 8; n++) {
            uint32_t bf0 = *reinterpret_cast<const uint32_t*>(&Ws2[(n * 8 + g) * SA + kc * 16 + 2 * th]);
            uint32_t bf1 = *reinterpret_cast<const uint32_t*>(&Ws2[(n * 8 + g) * SA + kc * 16 + 2 * th + 8]);
            mma_f16(acc2[n], a0, a1, a2, a3, bf0, bf1);
        }
    }

    // ---- bias + output ----
    int r0 = row0 + arow + g;
    int r1 = r0 + 8;
    bool v0 = (r0 < N_NODES);
    bool v1 = (r1 < N_NODES);

    if (mode == 0) {
#pragma unroll
        for (int n = 0; n < 8; n++) {
            int c = n * 8 + 2 * th;
            if (v0) {
                __half2 o = __floats2half2_rn(acc2[n][0] + b2s[c], acc2[n][1] + b2s[c + 1]);
                *reinterpret_cast<__half2*>(&hout[(size_t)r0 * D + c]) = o;
            }
            if (v1) {
                __half2 o = __floats2half2_rn(acc2[n][2] + b2s[c], acc2[n][3] + b2s[c + 1]);
                *reinterpret_cast<__half2*>(&hout[(size_t)r1 * D + c]) = o;
            }
        }
    } else {
        int gb0 = v0 ? batch[r0] : 0;
        int gb1 = v1 ? batch[r1] : 0;
        unsigned int* p0 = g_pool + (size_t)gb0 * D;
        unsigned int* p1 = g_pool + (size_t)gb1 * D;
#pragma unroll
        for (int n = 0; n < 8; n++) {
            int c = n * 8 + 2 * th;
#pragma unroll
            for (int j = 0; j < 4; j++) {
                float val = acc2[n][j] + b2s[c + (j & 1)];
                unsigned int bits = __float_as_uint(val);
                unsigned int enc = (bits & 0x80000000u) ? ~bits : (bits | 0x80000000u);
                if (j < 2) { if (v0) atomicMax(&p0[c + (j & 1)], enc); }
                else       { if (v1) atomicMax(&p1[c + (j & 1)], enc); }
            }
        }
    }
}

// ---------------------------------------------------------------------------
// FC head + log_softmax. One block (64 threads) per graph.
// ---------------------------------------------------------------------------
__global__ __launch_bounds__(64) void fc_kernel(const float* __restrict__ fcW1,
                                                const float* __restrict__ fcb1,
                                                const float* __restrict__ fcW2,
                                                const float* __restrict__ fcb2,
                                                float* __restrict__ out) {
    __shared__ float xr[D];
    __shared__ float hid[HID_FC];
    __shared__ float logits[N_CLASSES];
    __shared__ float m_s, lse_s;

    int g = blockIdx.x;
    int t = threadIdx.x;

    unsigned int e = g_pool[(size_t)g * D + t];
    unsigned int u = (e & 0x80000000u) ? (e & 0x7FFFFFFFu) : ~e;
    xr[t] = __uint_as_float(u);
    __syncthreads();

    float a = fcb1[t];
#pragma unroll
    for (int k = 0; k < D; k++) a += xr[k] * fcW1[k * HID_FC + t];
    hid[t] = fmaxf(a, 0.0f);
    __syncthreads();

    if (t < N_CLASSES) {
        float a2 = fcb2[t];
#pragma unroll
        for (int k = 0; k < HID_FC; k++) a2 += hid[k] * fcW2[k * N_CLASSES + t];
        logits[t] = a2;
    }
    __syncthreads();

    if (t == 0) {
        float m = logits[0];
#pragma unroll
        for (int j = 1; j < N_CLASSES; j++) m = fmaxf(m, logits[j]);
        float s = 0.0f;
#pragma unroll
        for (int j = 0; j < N_CLASSES; j++) s += expf(logits[j] - m);
        m_s = m;
        lse_s = logf(s);
    }
    __syncthreads();

    if (t < N_CLASSES) out[(size_t)g * N_CLASSES + t] = logits[t] - m_s - lse_s;
}

// ---------------------------------------------------------------------------
extern "C" void kernel_launch(void* const* d_in, const int* in_sizes, int n_in,
                              void* d_out, int out_size) {
    const float* x      = (const float*)d_in[0];
    const float* convW1 = (const float*)d_in[1];
    const float* convb1 = (const float*)d_in[2];
    const float* convW2 = (const float*)d_in[3];
    const float* convb2 = (const float*)d_in[4];
    const float* fcW1   = (const float*)d_in[5];
    const float* fcb1   = (const float*)d_in[6];
    const float* fcW2   = (const float*)d_in[7];
    const float* fcb2   = (const float*)d_in[8];
    const int* edge_index = (const int*)d_in[9];
    const int* batch      = (const int*)d_in[10];
    float* out = (float*)d_out;

    const int* src = edge_index;
    const int* dst = edge_index + N_EDGES;

    __half* xh_ptr = nullptr;
    __half* h_ptr = nullptr;
    __half* aggh_ptr = nullptr;
    int* cur_ptr = nullptr;
    __half* w1h_ptr = nullptr;
    __half* w2h_ptr = nullptr;
    cudaGetSymbolAddress((void**)&xh_ptr, g_xh);
    cudaGetSymbolAddress((void**)&h_ptr, g_h);
    cudaGetSymbolAddress((void**)&aggh_ptr, g_aggh);
    cudaGetSymbolAddress((void**)&cur_ptr, g_cur);
    cudaGetSymbolAddress((void**)&w1h_ptr, g_w1h);
    cudaGetSymbolAddress((void**)&w2h_ptr, g_w2h);

    const int e8_blocks = (N_EDGES / 8 + 255) / 256;         // 391
    const int gather_blocks = (N_NODES * 16 + 255) / 256;    // 3125
    const int mlp_blocks = (N_NODES + MROWS - 1) / MROWS;    // 391
    const int prep_blocks = (N_NODES * D / 2 + 255) / 256;   // covers all prep jobs

    // ---- per-replay setup ----
    cudaMemsetAsync(cur_ptr, 0, (size_t)N_NODES * sizeof(int));
    prep_kernel<<<prep_blocks, 256>>>(x, convW1, convW2);
    fill_kernel<<<e8_blocks, 256>>>(src, dst);

    // ---- 3 GIN layers (split gather / MLP; R10 structure) ----
    for (int l = 0; l < N_LAYERS; l++) {
        const __half* hin = (l == 0) ? xh_ptr : h_ptr;
        int mode = (l == N_LAYERS - 1) ? 1 : 0;
        gather_kernel<<<gather_blocks, 256>>>((const uint2*)hin, (uint2*)aggh_ptr);
        mlp_tc_kernel<<<mlp_blocks, 256>>>((const uint4*)aggh_ptr,
                                           w1h_ptr + (size_t)l * D * D, convb1 + (size_t)l * D,
                                           w2h_ptr + (size_t)l * D * D, convb2 + (size_t)l * D,
                                           h_ptr, batch, mode);
    }

    fc_kernel<<<N_GRAPHS, 64>>>(fcW1, fcb1, fcW2, fcb2, out);
}

// round 13
// speedup vs baseline: 1.3035x; 1.0519x over previous
#include <cuda_runtime.h>
#include <cuda_fp16.h>
#include <cstdint>

#define N_NODES 50000
#define N_EDGES 800000
#define D 64
#define N_GRAPHS 512
#define N_LAYERS 3
#define HID_FC 64
#define N_CLASSES 10
#define SA 72      // smem stride in HALVES for A and W tiles: frag banks 4g+th
#define CAP 128    // adjacency bucket capacity per node (mean deg = 16)
#define MROWS 128  // rows per MLP block

// Scratch (device globals: no allocations allowed)
__device__ __half g_xh[N_NODES * D];     // input x, fp16
__device__ __half g_h[N_NODES * D];      // layer activations, fp16
__device__ __half g_aggh[N_NODES * D];   // aggregated rows, fp16
__device__ unsigned int g_pool[N_GRAPHS * D];
__device__ int g_cur[N_NODES];
__device__ int g_adj[N_NODES * CAP];
__device__ __half g_w1h[N_LAYERS * D * D];  // W1 fp16, TRANSPOSED: [out n][in k]
__device__ __half g_w2h[N_LAYERS * D * D];  // W2 fp16, TRANSPOSED: [out n][in k]

// ---------------------------------------------------------------------------
__device__ __forceinline__ uint32_t pack_h2(float lo, float hi) {
    __half2 h = __floats2half2_rn(lo, hi);
    return *reinterpret_cast<uint32_t*>(&h);
}

__device__ __forceinline__ void acc8(float* a, uint4 v) {
    float2 f;
    f = __half22float2(*reinterpret_cast<const __half2*>(&v.x)); a[0] += f.x; a[1] += f.y;
    f = __half22float2(*reinterpret_cast<const __half2*>(&v.y)); a[2] += f.x; a[3] += f.y;
    f = __half22float2(*reinterpret_cast<const __half2*>(&v.z)); a[4] += f.x; a[5] += f.y;
    f = __half22float2(*reinterpret_cast<const __half2*>(&v.w)); a[6] += f.x; a[7] += f.y;
}

// ---------------------------------------------------------------------------
// Setup (once per replay): weights -> fp16 transposed, pool init, x -> fp16,
// AND adjacency bucket fill (g_cur zeroed by preceding memset).
// ---------------------------------------------------------------------------
__global__ void setup_kernel(const float* __restrict__ x,
                             const float* __restrict__ convW1,
                             const float* __restrict__ convW2,
                             const int* __restrict__ src,
                             const int* __restrict__ dst) {
    int i = blockIdx.x * blockDim.x + threadIdx.x;
    if (i < N_LAYERS * D * D) {
        int l = i >> 12;
        int rem = i & 4095;
        int n = rem >> 6;   // output col
        int k = rem & 63;   // input row
        g_w1h[i] = __float2half(convW1[(l << 12) + (k << 6) + n]);
        g_w2h[i] = __float2half(convW2[(l << 12) + (k << 6) + n]);
    }
    if (i < N_GRAPHS * D) g_pool[i] = 0x00800000u;  // encode(-FLT_MAX)
    if (i < N_NODES * D / 2) {
        float2 v = reinterpret_cast<const float2*>(x)[i];
        reinterpret_cast<__half2*>(g_xh)[i] = __floats2half2_rn(v.x, v.y);
    }
    if (i < N_EDGES / 8) {
        int e = i * 8;
        int4 d0 = *reinterpret_cast<const int4*>(dst + e);
        int4 d1 = *reinterpret_cast<const int4*>(dst + e + 4);
        int4 s0 = *reinterpret_cast<const int4*>(src + e);
        int4 s1 = *reinterpret_cast<const int4*>(src + e + 4);
        int p0 = atomicAdd(&g_cur[d0.x], 1);
        int p1 = atomicAdd(&g_cur[d0.y], 1);
        int p2 = atomicAdd(&g_cur[d0.z], 1);
        int p3 = atomicAdd(&g_cur[d0.w], 1);
        int p4 = atomicAdd(&g_cur[d1.x], 1);
        int p5 = atomicAdd(&g_cur[d1.y], 1);
        int p6 = atomicAdd(&g_cur[d1.z], 1);
        int p7 = atomicAdd(&g_cur[d1.w], 1);
        g_adj[d0.x * CAP + p0] = s0.x;
        g_adj[d0.y * CAP + p1] = s0.y;
        g_adj[d0.z * CAP + p2] = s0.z;
        g_adj[d0.w * CAP + p3] = s0.w;
        g_adj[d1.x * CAP + p4] = s1.x;
        g_adj[d1.y * CAP + p5] = s1.y;
        g_adj[d1.z * CAP + p6] = s1.z;
        g_adj[d1.w * CAP + p7] = s1.w;
    }
}

// ---------------------------------------------------------------------------
// Gather aggregation: aggh[n] = fp16(h[n] + sum_{j in N(n)} h[j]); h is fp16.
// 8 threads per node, one uint4 (16 B, 8 halves) per lane; fp32 accumulation.
// Per 8-neighbor round: 2 batches of 4 independent 16 B loads.
// ---------------------------------------------------------------------------
__global__ __launch_bounds__(256, 5) void gather_kernel(const uint4* __restrict__ hin4,
                                                        uint4* __restrict__ aggh4) {
    unsigned int gid = blockIdx.x * 256u + threadIdx.x;
    unsigned int node = gid >> 3;
    unsigned int lane = gid & 7u;
    if (node >= N_NODES) return;
    unsigned int hm = 0xFFu << (threadIdx.x & 24);  // this 8-lane segment

    float a[8];
    {
        uint4 s = hin4[(size_t)node * 8 + lane];  // self term (eps = 0)
        float2 f;
        f = __half22float2(*reinterpret_cast<const __half2*>(&s.x)); a[0] = f.x; a[1] = f.y;
        f = __half22float2(*reinterpret_cast<const __half2*>(&s.y)); a[2] = f.x; a[3] = f.y;
        f = __half22float2(*reinterpret_cast<const __half2*>(&s.z)); a[4] = f.x; a[5] = f.y;
        f = __half22float2(*reinterpret_cast<const __half2*>(&s.w)); a[6] = f.x; a[7] = f.y;
    }

    int cnt = g_cur[node];
    const int* adj = g_adj + (size_t)node * CAP;

    for (int base = 0; base < cnt; base += 8) {
        int my = base + (int)lane;
        int idx = (my < cnt) ? __ldg(adj + my) : 0;
        int m = cnt - base;
        if (m >= 8) {
#pragma unroll
            for (int j = 0; j < 8; j += 4) {
                int n0 = __shfl_sync(hm, idx, j + 0, 8);
                int n1 = __shfl_sync(hm, idx, j + 1, 8);
                int n2 = __shfl_sync(hm, idx, j + 2, 8);
                int n3 = __shfl_sync(hm, idx, j + 3, 8);
                uint4 v0 = hin4[(size_t)n0 * 8 + lane];
                uint4 v1 = hin4[(size_t)n1 * 8 + lane];
                uint4 v2 = hin4[(size_t)n2 * 8 + lane];
                uint4 v3 = hin4[(size_t)n3 * 8 + lane];
                acc8(a, v0);
                acc8(a, v1);
                acc8(a, v2);
                acc8(a, v3);
            }
        } else {
            for (int j = 0; j < m; j++) {
                int nb = __shfl_sync(hm, idx, j, 8);
                uint4 v = hin4[(size_t)nb * 8 + lane];
                acc8(a, v);
            }
        }
    }

    uint4 o;
    o.x = pack_h2(a[0], a[1]);
    o.y = pack_h2(a[2], a[3]);
    o.z = pack_h2(a[4], a[5]);
    o.w = pack_h2(a[6], a[7]);
    aggh4[(size_t)node * 8 + lane] = o;
}

// ---------------------------------------------------------------------------
// FP16 tensor-core fused MLP: h_out = relu(agg @ W1 + b1) @ W2 + b2
// mma.sync m16n8k16 f16.f16.f32. Block = 256 threads = 128 rows.
// W stored transposed [n][k]; GEMM2 A-frags == GEMM1 C-frags (same thread).
// mode 0: write hout (fp16); mode 1: fused global-max-pool into g_pool
// ---------------------------------------------------------------------------
__device__ __forceinline__ void mma_f16(float* c, uint32_t a0, uint32_t a1,
                                        uint32_t a2, uint32_t a3,
                                        uint32_t b0, uint32_t b1) {
    asm volatile(
        "mma.sync.aligned.m16n8k16.row.col.f32.f16.f16.f32 "
        "{%0,%1,%2,%3}, {%4,%5,%6,%7}, {%8,%9}, {%0,%1,%2,%3};"
        : "+f"(c[0]), "+f"(c[1]), "+f"(c[2]), "+f"(c[3])
        : "r"(a0), "r"(a1), "r"(a2), "r"(a3), "r"(b0), "r"(b1));
}

__global__ __launch_bounds__(256, 3) void mlp_tc_kernel(const uint4* __restrict__ xinh,
                                                        const __half* __restrict__ W1h,
                                                        const float* __restrict__ b1,
                                                        const __half* __restrict__ W2h,
                                                        const float* __restrict__ b2,
                                                        __half* __restrict__ hout,
                                                        const int* __restrict__ batch,
                                                        int mode) {
    __shared__ __half As[MROWS * SA];   // A tile (fp16)
    __shared__ __half Ws1[D * SA];      // W1^T (fp16)
    __shared__ __half Ws2[D * SA];      // W2^T (fp16)
    __shared__ float b1s[D];
    __shared__ float b2s[D];

    int tid = threadIdx.x;
    int warp = tid >> 5;
    int lane = tid & 31;
    int g = lane >> 2;   // group 0..7
    int th = lane & 3;   // thread-in-group 0..3
    int arow = warp * 16;
    int row0 = blockIdx.x * MROWS;

    // ---- stage A (128 rows x 8 uint4) + W1^T + W2^T ----
    for (int i = tid; i < MROWS * 8; i += 256) {
        int r = i >> 3;
        int c8 = (i & 7) << 3;
        uint4 t = make_uint4(0u, 0u, 0u, 0u);
        if (row0 + r < N_NODES)
            t = xinh[(size_t)(row0 + r) * 8 + (i & 7)];
        *reinterpret_cast<uint4*>(&As[r * SA + c8]) = t;
    }
    for (int i = tid; i < D * 8; i += 256) {
        int n = i >> 3;
        int c8 = (i & 7) << 3;
        uint4 t1 = reinterpret_cast<const uint4*>(W1h)[i];
        uint4 t2 = reinterpret_cast<const uint4*>(W2h)[i];
        *reinterpret_cast<uint4*>(&Ws1[n * SA + c8]) = t1;
        *reinterpret_cast<uint4*>(&Ws2[n * SA + c8]) = t2;
    }
    if (tid < D) { b1s[tid] = b1[tid]; b2s[tid] = b2[tid]; }
    __syncthreads();

    // ---- GEMM 1: acc = A @ W1  (4 k-chunks of 16) ----
    float acc[8][4];
#pragma unroll
    for (int n = 0; n < 8; n++)
#pragma unroll
        for (int j = 0; j < 4; j++) acc[n][j] = 0.f;

#pragma unroll
    for (int kc = 0; kc < 4; kc++) {
        uint32_t a0 = *reinterpret_cast<const uint32_t*>(&As[(arow + g) * SA + kc * 16 + 2 * th]);
        uint32_t a1 = *reinterpret_cast<const uint32_t*>(&As[(arow + g + 8) * SA + kc * 16 + 2 * th]);
        uint32_t a2 = *reinterpret_cast<const uint32_t*>(&As[(arow + g) * SA + kc * 16 + 2 * th + 8]);
        uint32_t a3 = *reinterpret_cast<const uint32_t*>(&As[(arow + g + 8) * SA + kc * 16 + 2 * th + 8]);
#pragma unroll
        for (int n = 0; n < 8; n++) {
            uint32_t bf0 = *reinterpret_cast<const uint32_t*>(&Ws1[(n * 8 + g) * SA + kc * 16 + 2 * th]);
            uint32_t bf1 = *reinterpret_cast<const uint32_t*>(&Ws1[(n * 8 + g) * SA + kc * 16 + 2 * th + 8]);
            mma_f16(acc[n], a0, a1, a2, a3, bf0, bf1);
        }
    }

    // ---- bias + relu (acc becomes T, fp32) ----
#pragma unroll
    for (int n = 0; n < 8; n++) {
        int c = n * 8 + 2 * th;
        acc[n][0] = fmaxf(acc[n][0] + b1s[c], 0.f);
        acc[n][1] = fmaxf(acc[n][1] + b1s[c + 1], 0.f);
        acc[n][2] = fmaxf(acc[n][2] + b1s[c], 0.f);
        acc[n][3] = fmaxf(acc[n][3] + b1s[c + 1], 0.f);
    }

    // ---- GEMM 2: acc2 = T @ W2; A-frags = own C-frags, cvt+pack only ----
    float acc2[8][4];
#pragma unroll
    for (int n = 0; n < 8; n++)
#pragma unroll
        for (int j = 0; j < 4; j++) acc2[n][j] = 0.f;

#pragma unroll
    for (int kc = 0; kc < 4; kc++) {
        uint32_t a0 = pack_h2(acc[2 * kc][0], acc[2 * kc][1]);
        uint32_t a1 = pack_h2(acc[2 * kc][2], acc[2 * kc][3]);
        uint32_t a2 = pack_h2(acc[2 * kc + 1][0], acc[2 * kc + 1][1]);
        uint32_t a3 = pack_h2(acc[2 * kc + 1][2], acc[2 * kc + 1][3]);
#pragma unroll
        for (int n = 0; n < 8; n++) {
            uint32_t bf0 = *reinterpret_cast<const uint32_t*>(&Ws2[(n * 8 + g) * SA + kc * 16 + 2 * th]);
            uint32_t bf1 = *reinterpret_cast<const uint32_t*>(&Ws2[(n * 8 + g) * SA + kc * 16 + 2 * th + 8]);
            mma_f16(acc2[n], a0, a1, a2, a3, bf0, bf1);
        }
    }

    // ---- bias + output ----
    int r0 = row0 + arow + g;
    int r1 = r0 + 8;
    bool v0 = (r0 < N_NODES);
    bool v1 = (r1 < N_NODES);

    if (mode == 0) {
#pragma unroll
        for (int n = 0; n < 8; n++) {
            int c = n * 8 + 2 * th;
            if (v0) {
                __half2 o = __floats2half2_rn(acc2[n][0] + b2s[c], acc2[n][1] + b2s[c + 1]);
                *reinterpret_cast<__half2*>(&hout[(size_t)r0 * D + c]) = o;
            }
            if (v1) {
                __half2 o = __floats2half2_rn(acc2[n][2] + b2s[c], acc2[n][3] + b2s[c + 1]);
                *reinterpret_cast<__half2*>(&hout[(size_t)r1 * D + c]) = o;
            }
        }
    } else {
        int gb0 = v0 ? batch[r0] : 0;
        int gb1 = v1 ? batch[r1] : 0;
        unsigned int* p0 = g_pool + (size_t)gb0 * D;
        unsigned int* p1 = g_pool + (size_t)gb1 * D;
#pragma unroll
        for (int n = 0; n < 8; n++) {
            int c = n * 8 + 2 * th;
#pragma unroll
            for (int j = 0; j < 4; j++) {
                float val = acc2[n][j] + b2s[c + (j & 1)];
                unsigned int bits = __float_as_uint(val);
                unsigned int enc = (bits & 0x80000000u) ? ~bits : (bits | 0x80000000u);
                if (j < 2) { if (v0) atomicMax(&p0[c + (j & 1)], enc); }
                else       { if (v1) atomicMax(&p1[c + (j & 1)], enc); }
            }
        }
    }
}

// ---------------------------------------------------------------------------
// FC head + log_softmax. One block (64 threads) per graph.
// ---------------------------------------------------------------------------
__global__ __launch_bounds__(64) void fc_kernel(const float* __restrict__ fcW1,
                                                const float* __restrict__ fcb1,
                                                const float* __restrict__ fcW2,
                                                const float* __restrict__ fcb2,
                                                float* __restrict__ out) {
    __shared__ float xr[D];
    __shared__ float hid[HID_FC];
    __shared__ float logits[N_CLASSES];
    __shared__ float m_s, lse_s;

    int g = blockIdx.x;
    int t = threadIdx.x;

    unsigned int e = g_pool[(size_t)g * D + t];
    unsigned int u = (e & 0x80000000u) ? (e & 0x7FFFFFFFu) : ~e;
    xr[t] = __uint_as_float(u);
    __syncthreads();

    float a = fcb1[t];
#pragma unroll
    for (int k = 0; k < D; k++) a += xr[k] * fcW1[k * HID_FC + t];
    hid[t] = fmaxf(a, 0.0f);
    __syncthreads();

    if (t < N_CLASSES) {
        float a2 = fcb2[t];
#pragma unroll
        for (int k = 0; k < HID_FC; k++) a2 += hid[k] * fcW2[k * N_CLASSES + t];
        logits[t] = a2;
    }
    __syncthreads();

    if (t == 0) {
        float m = logits[0];
#pragma unroll
        for (int j = 1; j < N_CLASSES; j++) m = fmaxf(m, logits[j]);
        float s = 0.0f;
#pragma unroll
        for (int j = 0; j < N_CLASSES; j++) s += expf(logits[j] - m);
        m_s = m;
        lse_s = logf(s);
    }
    __syncthreads();

    if (t < N_CLASSES) out[(size_t)g * N_CLASSES + t] = logits[t] - m_s - lse_s;
}

// ---------------------------------------------------------------------------
extern "C" void kernel_launch(void* const* d_in, const int* in_sizes, int n_in,
                              void* d_out, int out_size) {
    const float* x      = (const float*)d_in[0];
    const float* convW1 = (const float*)d_in[1];
    const float* convb1 = (const float*)d_in[2];
    const float* convW2 = (const float*)d_in[3];
    const float* convb2 = (const float*)d_in[4];
    const float* fcW1   = (const float*)d_in[5];
    const float* fcb1   = (const float*)d_in[6];
    const float* fcW2   = (const float*)d_in[7];
    const float* fcb2   = (const float*)d_in[8];
    const int* edge_index = (const int*)d_in[9];
    const int* batch      = (const int*)d_in[10];
    float* out = (float*)d_out;

    const int* src = edge_index;
    const int* dst = edge_index + N_EDGES;

    __half* xh_ptr = nullptr;
    __half* h_ptr = nullptr;
    __half* aggh_ptr = nullptr;
    int* cur_ptr = nullptr;
    __half* w1h_ptr = nullptr;
    __half* w2h_ptr = nullptr;
    cudaGetSymbolAddress((void**)&xh_ptr, g_xh);
    cudaGetSymbolAddress((void**)&h_ptr, g_h);
    cudaGetSymbolAddress((void**)&aggh_ptr, g_aggh);
    cudaGetSymbolAddress((void**)&cur_ptr, g_cur);
    cudaGetSymbolAddress((void**)&w1h_ptr, g_w1h);
    cudaGetSymbolAddress((void**)&w2h_ptr, g_w2h);

    const int gather_blocks = (N_NODES * 8 + 255) / 256;     // 1563
    const int mlp_blocks = (N_NODES + MROWS - 1) / MROWS;    // 391
    const int setup_blocks = (N_NODES * D / 2 + 255) / 256;  // 6250 (covers all setup jobs)

    // ---- per-replay setup ----
    cudaMemsetAsync(cur_ptr, 0, (size_t)N_NODES * sizeof(int));
    setup_kernel<<<setup_blocks, 256>>>(x, convW1, convW2, src, dst);

    // ---- 3 GIN layers ----
    for (int l = 0; l < N_LAYERS; l++) {
        const __half* hin = (l == 0) ? xh_ptr : h_ptr;
        int mode = (l == N_LAYERS - 1) ? 1 : 0;
        gather_kernel<<<gather_blocks, 256>>>((const uint4*)hin, (uint4*)aggh_ptr);
        mlp_tc_kernel<<<mlp_blocks, 256>>>((const uint4*)aggh_ptr,
                                           w1h_ptr + (size_t)l * D * D, convb1 + (size_t)l * D,
                                           w2h_ptr + (size_t)l * D * D, convb2 + (size_t)l * D,
                                           h_ptr, batch, mode);
    }

    fc_kernel<<<N_GRAPHS, 64>>>(fcW1, fcb1, fcW2, fcb2, out);
}

// round 14
// speedup vs baseline: 1.4877x; 1.1414x over previous
#include <cuda_runtime.h>
#include <cuda_fp16.h>
#include <cstdint>

#define N_NODES 50000
#define N_EDGES 800000
#define D 64
#define N_GRAPHS 512
#define N_LAYERS 3
#define HID_FC 64
#define N_CLASSES 10
#define SA 72      // smem stride in HALVES for A and W tiles: frag banks 4g+th
#define CAP 128    // adjacency bucket capacity per node (mean deg = 16)
#define MROWS 128  // rows per MLP block

// Scratch (device globals: no allocations allowed)
__device__ __half g_xh[N_NODES * D];     // input x, fp16
__device__ __half g_h[N_NODES * D];      // layer activations, fp16
__device__ __half g_aggh[N_NODES * D];   // aggregated rows, fp16
__device__ unsigned int g_pool[N_GRAPHS * D];
__device__ int g_cur[N_NODES];
__device__ int g_adj[N_NODES * CAP];
__device__ __half g_w1h[N_LAYERS * D * D];  // W1 fp16, TRANSPOSED: [out n][in k]
__device__ __half g_w2h[N_LAYERS * D * D];  // W2 fp16, TRANSPOSED: [out n][in k]

// ---------------------------------------------------------------------------
__device__ __forceinline__ uint32_t pack_h2(float lo, float hi) {
    __half2 h = __floats2half2_rn(lo, hi);
    return *reinterpret_cast<uint32_t*>(&h);
}

__device__ __forceinline__ __half2 u2h2(uint32_t u) {
    return *reinterpret_cast<const __half2*>(&u);
}

// accumulate one fp16 row (uint4 = 8 halves) into fp32 accumulators
__device__ __forceinline__ void acc8(float* a, uint4 v) {
    float2 f;
    f = __half22float2(u2h2(v.x)); a[0] += f.x; a[1] += f.y;
    f = __half22float2(u2h2(v.y)); a[2] += f.x; a[3] += f.y;
    f = __half22float2(u2h2(v.z)); a[4] += f.x; a[5] += f.y;
    f = __half22float2(u2h2(v.w)); a[6] += f.x; a[7] += f.y;
}

// accumulate PAIR of fp16 rows: fp16 pre-add (full-rate), single cvt per pair
__device__ __forceinline__ void acc_pair(float* a, uint4 v0, uint4 v1) {
    float2 f;
    f = __half22float2(__hadd2(u2h2(v0.x), u2h2(v1.x))); a[0] += f.x; a[1] += f.y;
    f = __half22float2(__hadd2(u2h2(v0.y), u2h2(v1.y))); a[2] += f.x; a[3] += f.y;
    f = __half22float2(__hadd2(u2h2(v0.z), u2h2(v1.z))); a[4] += f.x; a[5] += f.y;
    f = __half22float2(__hadd2(u2h2(v0.w), u2h2(v1.w))); a[6] += f.x; a[7] += f.y;
}

// ---------------------------------------------------------------------------
// Setup (once per replay): weights -> fp16 transposed, pool init, x -> fp16,
// AND adjacency bucket fill (g_cur zeroed by preceding memset).
// ---------------------------------------------------------------------------
__global__ void setup_kernel(const float* __restrict__ x,
                             const float* __restrict__ convW1,
                             const float* __restrict__ convW2,
                             const int* __restrict__ src,
                             const int* __restrict__ dst) {
    int i = blockIdx.x * blockDim.x + threadIdx.x;
    if (i < N_LAYERS * D * D) {
        int l = i >> 12;
        int rem = i & 4095;
        int n = rem >> 6;   // output col
        int k = rem & 63;   // input row
        g_w1h[i] = __float2half(convW1[(l << 12) + (k << 6) + n]);
        g_w2h[i] = __float2half(convW2[(l << 12) + (k << 6) + n]);
    }
    if (i < N_GRAPHS * D) g_pool[i] = 0x00800000u;  // encode(-FLT_MAX)
    if (i < N_NODES * D / 2) {
        float2 v = reinterpret_cast<const float2*>(x)[i];
        reinterpret_cast<__half2*>(g_xh)[i] = __floats2half2_rn(v.x, v.y);
    }
    if (i < N_EDGES / 8) {
        int e = i * 8;
        int4 d0 = *reinterpret_cast<const int4*>(dst + e);
        int4 d1 = *reinterpret_cast<const int4*>(dst + e + 4);
        int4 s0 = *reinterpret_cast<const int4*>(src + e);
        int4 s1 = *reinterpret_cast<const int4*>(src + e + 4);
        int p0 = atomicAdd(&g_cur[d0.x], 1);
        int p1 = atomicAdd(&g_cur[d0.y], 1);
        int p2 = atomicAdd(&g_cur[d0.z], 1);
        int p3 = atomicAdd(&g_cur[d0.w], 1);
        int p4 = atomicAdd(&g_cur[d1.x], 1);
        int p5 = atomicAdd(&g_cur[d1.y], 1);
        int p6 = atomicAdd(&g_cur[d1.z], 1);
        int p7 = atomicAdd(&g_cur[d1.w], 1);
        g_adj[d0.x * CAP + p0] = s0.x;
        g_adj[d0.y * CAP + p1] = s0.y;
        g_adj[d0.z * CAP + p2] = s0.z;
        g_adj[d0.w * CAP + p3] = s0.w;
        g_adj[d1.x * CAP + p4] = s1.x;
        g_adj[d1.y * CAP + p5] = s1.y;
        g_adj[d1.z * CAP + p6] = s1.z;
        g_adj[d1.w * CAP + p7] = s1.w;
    }
}

// ---------------------------------------------------------------------------
// Gather aggregation: aggh[n] = fp16(h[n] + sum_{j in N(n)} h[j]); h is fp16.
// 8 threads per node, one uint4 (16 B, 8 halves) per lane; pairs of neighbor
// rows pre-added in fp16 (HADD2) -> one cvt per pair -> fp32 accumulate.
// ---------------------------------------------------------------------------
__global__ __launch_bounds__(256, 5) void gather_kernel(const uint4* __restrict__ hin4,
                                                        uint4* __restrict__ aggh4) {
    unsigned int gid = blockIdx.x * 256u + threadIdx.x;
    unsigned int node = gid >> 3;
    unsigned int lane = gid & 7u;
    if (node >= N_NODES) return;
    unsigned int hm = 0xFFu << (threadIdx.x & 24);  // this 8-lane segment

    float a[8];
    {
        uint4 s = hin4[(size_t)node * 8 + lane];  // self term (eps = 0)
        float2 f;
        f = __half22float2(u2h2(s.x)); a[0] = f.x; a[1] = f.y;
        f = __half22float2(u2h2(s.y)); a[2] = f.x; a[3] = f.y;
        f = __half22float2(u2h2(s.z)); a[4] = f.x; a[5] = f.y;
        f = __half22float2(u2h2(s.w)); a[6] = f.x; a[7] = f.y;
    }

    int cnt = g_cur[node];
    const int* adj = g_adj + (size_t)node * CAP;

    for (int base = 0; base < cnt; base += 8) {
        int my = base + (int)lane;
        int idx = (my < cnt) ? __ldg(adj + my) : 0;
        int m = cnt - base;
        if (m >= 8) {
#pragma unroll
            for (int j = 0; j < 8; j += 4) {
                int n0 = __shfl_sync(hm, idx, j + 0, 8);
                int n1 = __shfl_sync(hm, idx, j + 1, 8);
                int n2 = __shfl_sync(hm, idx, j + 2, 8);
                int n3 = __shfl_sync(hm, idx, j + 3, 8);
                uint4 v0 = hin4[(size_t)n0 * 8 + lane];
                uint4 v1 = hin4[(size_t)n1 * 8 + lane];
                uint4 v2 = hin4[(size_t)n2 * 8 + lane];
                uint4 v3 = hin4[(size_t)n3 * 8 + lane];
                acc_pair(a, v0, v1);
                acc_pair(a, v2, v3);
            }
        } else {
            int j = 0;
            for (; j + 1 < m; j += 2) {
                int na = __shfl_sync(hm, idx, j, 8);
                int nb = __shfl_sync(hm, idx, j + 1, 8);
                uint4 va = hin4[(size_t)na * 8 + lane];
                uint4 vb = hin4[(size_t)nb * 8 + lane];
                acc_pair(a, va, vb);
            }
            if (j < m) {
                int nb = __shfl_sync(hm, idx, j, 8);
                uint4 v = hin4[(size_t)nb * 8 + lane];
                acc8(a, v);
            }
        }
    }

    uint4 o;
    o.x = pack_h2(a[0], a[1]);
    o.y = pack_h2(a[2], a[3]);
    o.z = pack_h2(a[4], a[5]);
    o.w = pack_h2(a[6], a[7]);
    aggh4[(size_t)node * 8 + lane] = o;
}

// ---------------------------------------------------------------------------
// FP16 tensor-core fused MLP: h_out = relu(agg @ W1 + b1) @ W2 + b2
// mma.sync m16n8k16 f16.f16.f32. Block = 256 threads = 128 rows.
// W stored transposed [n][k]; GEMM2 A-frags == GEMM1 C-frags (same thread).
// mode 0: write hout (fp16); mode 1: fused global-max-pool into g_pool
// ---------------------------------------------------------------------------
__device__ __forceinline__ void mma_f16(float* c, uint32_t a0, uint32_t a1,
                                        uint32_t a2, uint32_t a3,
                                        uint32_t b0, uint32_t b1) {
    asm volatile(
        "mma.sync.aligned.m16n8k16.row.col.f32.f16.f16.f32 "
        "{%0,%1,%2,%3}, {%4,%5,%6,%7}, {%8,%9}, {%0,%1,%2,%3};"
        : "+f"(c[0]), "+f"(c[1]), "+f"(c[2]), "+f"(c[3])
        : "r"(a0), "r"(a1), "r"(a2), "r"(a3), "r"(b0), "r"(b1));
}

__global__ __launch_bounds__(256, 3) void mlp_tc_kernel(const uint4* __restrict__ xinh,
                                                        const __half* __restrict__ W1h,
                                                        const float* __restrict__ b1,
                                                        const __half* __restrict__ W2h,
                                                        const float* __restrict__ b2,
                                                        __half* __restrict__ hout,
                                                        const int* __restrict__ batch,
                                                        int mode) {
    __shared__ __half As[MROWS * SA];   // A tile (fp16)
    __shared__ __half Ws1[D * SA];      // W1^T (fp16)
    __shared__ __half Ws2[D * SA];      // W2^T (fp16)
    __shared__ float b1s[D];
    __shared__ float b2s[D];

    int tid = threadIdx.x;
    int warp = tid >> 5;
    int lane = tid & 31;
    int g = lane >> 2;   // group 0..7
    int th = lane & 3;   // thread-in-group 0..3
    int arow = warp * 16;
    int row0 = blockIdx.x * MROWS;

    // ---- stage A (128 rows x 8 uint4) + W1^T + W2^T ----
    for (int i = tid; i < MROWS * 8; i += 256) {
        int r = i >> 3;
        int c8 = (i & 7) << 3;
        uint4 t = make_uint4(0u, 0u, 0u, 0u);
        if (row0 + r < N_NODES)
            t = xinh[(size_t)(row0 + r) * 8 + (i & 7)];
        *reinterpret_cast<uint4*>(&As[r * SA + c8]) = t;
    }
    for (int i = tid; i < D * 8; i += 256) {
        int n = i >> 3;
        int c8 = (i & 7) << 3;
        uint4 t1 = reinterpret_cast<const uint4*>(W1h)[i];
        uint4 t2 = reinterpret_cast<const uint4*>(W2h)[i];
        *reinterpret_cast<uint4*>(&Ws1[n * SA + c8]) = t1;
        *reinterpret_cast<uint4*>(&Ws2[n * SA + c8]) = t2;
    }
    if (tid < D) { b1s[tid] = b1[tid]; b2s[tid] = b2[tid]; }
    __syncthreads();

    // ---- GEMM 1: acc = A @ W1  (4 k-chunks of 16) ----
    float acc[8][4];
#pragma unroll
    for (int n = 0; n < 8; n++)
#pragma unroll
        for (int j = 0; j < 4; j++) acc[n][j] = 0.f;

#pragma unroll
    for (int kc = 0; kc < 4; kc++) {
        uint32_t a0 = *reinterpret_cast<const uint32_t*>(&As[(arow + g) * SA + kc * 16 + 2 * th]);
        uint32_t a1 = *reinterpret_cast<const uint32_t*>(&As[(arow + g + 8) * SA + kc * 16 + 2 * th]);
        uint32_t a2 = *reinterpret_cast<const uint32_t*>(&As[(arow + g) * SA + kc * 16 + 2 * th + 8]);
        uint32_t a3 = *reinterpret_cast<const uint32_t*>(&As[(arow + g + 8) * SA + kc * 16 + 2 * th + 8]);
#pragma unroll
        for (int n = 0; n < 8; n++) {
            uint32_t bf0 = *reinterpret_cast<const uint32_t*>(&Ws1[(n * 8 + g) * SA + kc * 16 + 2 * th]);
            uint32_t bf1 = *reinterpret_cast<const uint32_t*>(&Ws1[(n * 8 + g) * SA + kc * 16 + 2 * th + 8]);
            mma_f16(acc[n], a0, a1, a2, a3, bf0, bf1);
        }
    }

    // ---- bias + relu (acc becomes T, fp32) ----
#pragma unroll
    for (int n = 0; n < 8; n++) {
        int c = n * 8 + 2 * th;
        acc[n][0] = fmaxf(acc[n][0] + b1s[c], 0.f);
        acc[n][1] = fmaxf(acc[n][1] + b1s[c + 1], 0.f);
        acc[n][2] = fmaxf(acc[n][2] + b1s[c], 0.f);
        acc[n][3] = fmaxf(acc[n][3] + b1s[c + 1], 0.f);
    }

    // ---- GEMM 2: acc2 = T @ W2; A-frags = own C-frags, cvt+pack only ----
    float acc2[8][4];
#pragma unroll
    for (int n = 0; n < 8; n++)
#pragma unroll
        for (int j = 0; j < 4; j++) acc2[n][j] = 0.f;

#pragma unroll
    for (int kc = 0; kc < 4; kc++) {
        uint32_t a0 = pack_h2(acc[2 * kc][0], acc[2 * kc][1]);
        uint32_t a1 = pack_h2(acc[2 * kc][2], acc[2 * kc][3]);
        uint32_t a2 = pack_h2(acc[2 * kc + 1][0], acc[2 * kc + 1][1]);
        uint32_t a3 = pack_h2(acc[2 * kc + 1][2], acc[2 * kc + 1][3]);
#pragma unroll
        for (int n = 0; n < 8; n++) {
            uint32_t bf0 = *reinterpret_cast<const uint32_t*>(&Ws2[(n * 8 + g) * SA + kc * 16 + 2 * th]);
            uint32_t bf1 = *reinterpret_cast<const uint32_t*>(&Ws2[(n * 8 + g) * SA + kc * 16 + 2 * th + 8]);
            mma_f16(acc2[n], a0, a1, a2, a3, bf0, bf1);
        }
    }

    // ---- bias + output ----
    int r0 = row0 + arow + g;
    int r1 = r0 + 8;
    bool v0 = (r0 < N_NODES);
    bool v1 = (r1 < N_NODES);

    if (mode == 0) {
#pragma unroll
        for (int n = 0; n < 8; n++) {
            int c = n * 8 + 2 * th;
            if (v0) {
                __half2 o = __floats2half2_rn(acc2[n][0] + b2s[c], acc2[n][1] + b2s[c + 1]);
                *reinterpret_cast<__half2*>(&hout[(size_t)r0 * D + c]) = o;
            }
            if (v1) {
                __half2 o = __floats2half2_rn(acc2[n][2] + b2s[c], acc2[n][3] + b2s[c + 1]);
                *reinterpret_cast<__half2*>(&hout[(size_t)r1 * D + c]) = o;
            }
        }
    } else {
        int gb0 = v0 ? batch[r0] : 0;
        int gb1 = v1 ? batch[r1] : 0;
        unsigned int* p0 = g_pool + (size_t)gb0 * D;
        unsigned int* p1 = g_pool + (size_t)gb1 * D;
#pragma unroll
        for (int n = 0; n < 8; n++) {
            int c = n * 8 + 2 * th;
#pragma unroll
            for (int j = 0; j < 4; j++) {
                float val = acc2[n][j] + b2s[c + (j & 1)];
                unsigned int bits = __float_as_uint(val);
                unsigned int enc = (bits & 0x80000000u) ? ~bits : (bits | 0x80000000u);
                if (j < 2) { if (v0) atomicMax(&p0[c + (j & 1)], enc); }
                else       { if (v1) atomicMax(&p1[c + (j & 1)], enc); }
            }
        }
    }
}

// ---------------------------------------------------------------------------
// FC head + log_softmax. One block (64 threads) per graph.
// ---------------------------------------------------------------------------
__global__ __launch_bounds__(64) void fc_kernel(const float* __restrict__ fcW1,
                                                const float* __restrict__ fcb1,
                                                const float* __restrict__ fcW2,
                                                const float* __restrict__ fcb2,
                                                float* __restrict__ out) {
    __shared__ float xr[D];
    __shared__ float hid[HID_FC];
    __shared__ float logits[N_CLASSES];
    __shared__ float m_s, lse_s;

    int g = blockIdx.x;
    int t = threadIdx.x;

    unsigned int e = g_pool[(size_t)g * D + t];
    unsigned int u = (e & 0x80000000u) ? (e & 0x7FFFFFFFu) : ~e;
    xr[t] = __uint_as_float(u);
    __syncthreads();

    float a = fcb1[t];
#pragma unroll
    for (int k = 0; k < D; k++) a += xr[k] * fcW1[k * HID_FC + t];
    hid[t] = fmaxf(a, 0.0f);
    __syncthreads();

    if (t < N_CLASSES) {
        float a2 = fcb2[t];
#pragma unroll
        for (int k = 0; k < HID_FC; k++) a2 += hid[k] * fcW2[k * N_CLASSES + t];
        logits[t] = a2;
    }
    __syncthreads();

    if (t == 0) {
        float m = logits[0];
#pragma unroll
        for (int j = 1; j < N_CLASSES; j++) m = fmaxf(m, logits[j]);
        float s = 0.0f;
#pragma unroll
        for (int j = 0; j < N_CLASSES; j++) s += expf(logits[j] - m);
        m_s = m;
        lse_s = logf(s);
    }
    __syncthreads();

    if (t < N_CLASSES) out[(size_t)g * N_CLASSES + t] = logits[t] - m_s - lse_s;
}

// ---------------------------------------------------------------------------
extern "C" void kernel_launch(void* const* d_in, const int* in_sizes, int n_in,
                              void* d_out, int out_size) {
    const float* x      = (const float*)d_in[0];
    const float* convW1 = (const float*)d_in[1];
    const float* convb1 = (const float*)d_in[2];
    const float* convW2 = (const float*)d_in[3];
    const float* convb2 = (const float*)d_in[4];
    const float* fcW1   = (const float*)d_in[5];
    const float* fcb1   = (const float*)d_in[6];
    const float* fcW2   = (const float*)d_in[7];
    const float* fcb2   = (const float*)d_in[8];
    const int* edge_index = (const int*)d_in[9];
    const int* batch      = (const int*)d_in[10];
    float* out = (float*)d_out;

    const int* src = edge_index;
    const int* dst = edge_index + N_EDGES;

    __half* xh_ptr = nullptr;
    __half* h_ptr = nullptr;
    __half* aggh_ptr = nullptr;
    int* cur_ptr = nullptr;
    __half* w1h_ptr = nullptr;
    __half* w2h_ptr = nullptr;
    cudaGetSymbolAddress((void**)&xh_ptr, g_xh);
    cudaGetSymbolAddress((void**)&h_ptr, g_h);
    cudaGetSymbolAddress((void**)&aggh_ptr, g_aggh);
    cudaGetSymbolAddress((void**)&cur_ptr, g_cur);
    cudaGetSymbolAddress((void**)&w1h_ptr, g_w1h);
    cudaGetSymbolAddress((void**)&w2h_ptr, g_w2h);

    const int gather_blocks = (N_NODES * 8 + 255) / 256;     // 1563
    const int mlp_blocks = (N_NODES + MROWS - 1) / MROWS;    // 391
    const int setup_blocks = (N_NODES * D / 2 + 255) / 256;  // covers all setup jobs

    // ---- per-replay setup ----
    cudaMemsetAsync(cur_ptr, 0, (size_t)N_NODES * sizeof(int));
    setup_kernel<<<setup_blocks, 256>>>(x, convW1, convW2, src, dst);

    // ---- 3 GIN layers ----
    for (int l = 0; l < N_LAYERS; l++) {
        const __half* hin = (l == 0) ? xh_ptr : h_ptr;
        int mode = (l == N_LAYERS - 1) ? 1 : 0;
        gather_kernel<<<gather_blocks, 256>>>((const uint4*)hin, (uint4*)aggh_ptr);
        mlp_tc_kernel<<<mlp_blocks, 256>>>((const uint4*)aggh_ptr,
                                           w1h_ptr + (size_t)l * D * D, convb1 + (size_t)l * D,
                                           w2h_ptr + (size_t)l * D * D, convb2 + (size_t)l * D,
                                           h_ptr, batch, mode);
    }

    fc_kernel<<<N_GRAPHS, 64>>>(fcW1, fcb1, fcW2, fcb2, out);
}

// round 15
// speedup vs baseline: 1.4896x; 1.0013x over previous
#include <cuda_runtime.h>
#include <cuda_fp16.h>
#include <cstdint>

#define N_NODES 50000
#define N_EDGES 800000
#define D 64
#define N_GRAPHS 512
#define N_LAYERS 3
#define HID_FC 64
#define N_CLASSES 10
#define SA 72      // smem stride in HALVES for A and W tiles: frag banks 4g+th
#define CAP 128    // adjacency bucket capacity per node (mean deg = 16)
#define MROWS 128  // rows per MLP block

// Scratch (device globals: no allocations allowed)
__device__ __half g_xh[N_NODES * D];     // input x, fp16
__device__ __half g_h[N_NODES * D];      // layer activations, fp16
__device__ __half g_aggh[N_NODES * D];   // aggregated rows, fp16
__device__ unsigned int g_pool[N_GRAPHS * D];
__device__ int g_cur[N_NODES];
__device__ int g_adj[N_NODES * CAP];
__device__ __half g_w1h[N_LAYERS * D * D];  // W1 fp16, TRANSPOSED: [out n][in k]
__device__ __half g_w2h[N_LAYERS * D * D];  // W2 fp16, TRANSPOSED: [out n][in k]

// ---------------------------------------------------------------------------
__device__ __forceinline__ uint32_t pack_h2(float lo, float hi) {
    __half2 h = __floats2half2_rn(lo, hi);
    return *reinterpret_cast<uint32_t*>(&h);
}

__device__ __forceinline__ __half2 u2h2(uint32_t u) {
    return *reinterpret_cast<const __half2*>(&u);
}

// accumulate one fp16 row (uint4 = 8 halves) into fp32 accumulators
__device__ __forceinline__ void acc8(float* a, uint4 v) {
    float2 f;
    f = __half22float2(u2h2(v.x)); a[0] += f.x; a[1] += f.y;
    f = __half22float2(u2h2(v.y)); a[2] += f.x; a[3] += f.y;
    f = __half22float2(u2h2(v.z)); a[4] += f.x; a[5] += f.y;
    f = __half22float2(u2h2(v.w)); a[6] += f.x; a[7] += f.y;
}

// accumulate PAIR of fp16 rows: one HADD2 level, one cvt per pair
__device__ __forceinline__ void acc_pair(float* a, uint4 v0, uint4 v1) {
    float2 f;
    f = __half22float2(__hadd2(u2h2(v0.x), u2h2(v1.x))); a[0] += f.x; a[1] += f.y;
    f = __half22float2(__hadd2(u2h2(v0.y), u2h2(v1.y))); a[2] += f.x; a[3] += f.y;
    f = __half22float2(__hadd2(u2h2(v0.z), u2h2(v1.z))); a[4] += f.x; a[5] += f.y;
    f = __half22float2(__hadd2(u2h2(v0.w), u2h2(v1.w))); a[6] += f.x; a[7] += f.y;
}

// accumulate QUAD of fp16 rows: two HADD2 levels, one cvt per quad
__device__ __forceinline__ void acc_quad(float* a, uint4 v0, uint4 v1,
                                         uint4 v2, uint4 v3) {
    float2 f;
    f = __half22float2(__hadd2(__hadd2(u2h2(v0.x), u2h2(v1.x)),
                               __hadd2(u2h2(v2.x), u2h2(v3.x))));
    a[0] += f.x; a[1] += f.y;
    f = __half22float2(__hadd2(__hadd2(u2h2(v0.y), u2h2(v1.y)),
                               __hadd2(u2h2(v2.y), u2h2(v3.y))));
    a[2] += f.x; a[3] += f.y;
    f = __half22float2(__hadd2(__hadd2(u2h2(v0.z), u2h2(v1.z)),
                               __hadd2(u2h2(v2.z), u2h2(v3.z))));
    a[4] += f.x; a[5] += f.y;
    f = __half22float2(__hadd2(__hadd2(u2h2(v0.w), u2h2(v1.w)),
                               __hadd2(u2h2(v2.w), u2h2(v3.w))));
    a[6] += f.x; a[7] += f.y;
}

// ---------------------------------------------------------------------------
// Setup (once per replay): weights -> fp16 transposed, pool init, x -> fp16,
// AND adjacency bucket fill (g_cur zeroed by preceding memset).
// ---------------------------------------------------------------------------
__global__ void setup_kernel(const float* __restrict__ x,
                             const float* __restrict__ convW1,
                             const float* __restrict__ convW2,
                             const int* __restrict__ src,
                             const int* __restrict__ dst) {
    int i = blockIdx.x * blockDim.x + threadIdx.x;
    if (i < N_LAYERS * D * D) {
        int l = i >> 12;
        int rem = i & 4095;
        int n = rem >> 6;   // output col
        int k = rem & 63;   // input row
        g_w1h[i] = __float2half(convW1[(l << 12) + (k << 6) + n]);
        g_w2h[i] = __float2half(convW2[(l << 12) + (k << 6) + n]);
    }
    if (i < N_GRAPHS * D) g_pool[i] = 0x00800000u;  // encode(-FLT_MAX)
    if (i < N_NODES * D / 2) {
        float2 v = reinterpret_cast<const float2*>(x)[i];
        reinterpret_cast<__half2*>(g_xh)[i] = __floats2half2_rn(v.x, v.y);
    }
    if (i < N_EDGES / 8) {
        int e = i * 8;
        int4 d0 = *reinterpret_cast<const int4*>(dst + e);
        int4 d1 = *reinterpret_cast<const int4*>(dst + e + 4);
        int4 s0 = *reinterpret_cast<const int4*>(src + e);
        int4 s1 = *reinterpret_cast<const int4*>(src + e + 4);
        int p0 = atomicAdd(&g_cur[d0.x], 1);
        int p1 = atomicAdd(&g_cur[d0.y], 1);
        int p2 = atomicAdd(&g_cur[d0.z], 1);
        int p3 = atomicAdd(&g_cur[d0.w], 1);
        int p4 = atomicAdd(&g_cur[d1.x], 1);
        int p5 = atomicAdd(&g_cur[d1.y], 1);
        int p6 = atomicAdd(&g_cur[d1.z], 1);
        int p7 = atomicAdd(&g_cur[d1.w], 1);
        g_adj[d0.x * CAP + p0] = s0.x;
        g_adj[d0.y * CAP + p1] = s0.y;
        g_adj[d0.z * CAP + p2] = s0.z;
        g_adj[d0.w * CAP + p3] = s0.w;
        g_adj[d1.x * CAP + p4] = s1.x;
        g_adj[d1.y * CAP + p5] = s1.y;
        g_adj[d1.z * CAP + p6] = s1.z;
        g_adj[d1.w * CAP + p7] = s1.w;
    }
}

// ---------------------------------------------------------------------------
// Gather aggregation: aggh[n] = fp16(h[n] + sum_{j in N(n)} h[j]); h is fp16.
// 8 threads per node, one uint4 (16 B, 8 halves) per lane; QUADS of neighbor
// rows pre-added via 2-level fp16 tree -> one cvt per quad -> fp32 accumulate.
// ---------------------------------------------------------------------------
__global__ __launch_bounds__(256, 6) void gather_kernel(const uint4* __restrict__ hin4,
                                                        uint4* __restrict__ aggh4) {
    unsigned int gid = blockIdx.x * 256u + threadIdx.x;
    unsigned int node = gid >> 3;
    unsigned int lane = gid & 7u;
    if (node >= N_NODES) return;
    unsigned int hm = 0xFFu << (threadIdx.x & 24);  // this 8-lane segment

    float a[8];
    {
        uint4 s = hin4[(size_t)node * 8 + lane];  // self term (eps = 0)
        float2 f;
        f = __half22float2(u2h2(s.x)); a[0] = f.x; a[1] = f.y;
        f = __half22float2(u2h2(s.y)); a[2] = f.x; a[3] = f.y;
        f = __half22float2(u2h2(s.z)); a[4] = f.x; a[5] = f.y;
        f = __half22float2(u2h2(s.w)); a[6] = f.x; a[7] = f.y;
    }

    int cnt = g_cur[node];
    const int* adj = g_adj + (size_t)node * CAP;

    for (int base = 0; base < cnt; base += 8) {
        int my = base + (int)lane;
        int idx = (my < cnt) ? __ldg(adj + my) : 0;
        int m = cnt - base;
        if (m >= 8) {
#pragma unroll
            for (int j = 0; j < 8; j += 4) {
                int n0 = __shfl_sync(hm, idx, j + 0, 8);
                int n1 = __shfl_sync(hm, idx, j + 1, 8);
                int n2 = __shfl_sync(hm, idx, j + 2, 8);
                int n3 = __shfl_sync(hm, idx, j + 3, 8);
                uint4 v0 = hin4[(size_t)n0 * 8 + lane];
                uint4 v1 = hin4[(size_t)n1 * 8 + lane];
                uint4 v2 = hin4[(size_t)n2 * 8 + lane];
                uint4 v3 = hin4[(size_t)n3 * 8 + lane];
                acc_quad(a, v0, v1, v2, v3);
            }
        } else {
            int j = 0;
            for (; j + 3 < m; j += 4) {
                int n0 = __shfl_sync(hm, idx, j + 0, 8);
                int n1 = __shfl_sync(hm, idx, j + 1, 8);
                int n2 = __shfl_sync(hm, idx, j + 2, 8);
                int n3 = __shfl_sync(hm, idx, j + 3, 8);
                uint4 v0 = hin4[(size_t)n0 * 8 + lane];
                uint4 v1 = hin4[(size_t)n1 * 8 + lane];
                uint4 v2 = hin4[(size_t)n2 * 8 + lane];
                uint4 v3 = hin4[(size_t)n3 * 8 + lane];
                acc_quad(a, v0, v1, v2, v3);
            }
            for (; j + 1 < m; j += 2) {
                int na = __shfl_sync(hm, idx, j, 8);
                int nb = __shfl_sync(hm, idx, j + 1, 8);
                uint4 va = hin4[(size_t)na * 8 + lane];
                uint4 vb = hin4[(size_t)nb * 8 + lane];
                acc_pair(a, va, vb);
            }
            if (j < m) {
                int nb = __shfl_sync(hm, idx, j, 8);
                uint4 v = hin4[(size_t)nb * 8 + lane];
                acc8(a, v);
            }
        }
    }

    uint4 o;
    o.x = pack_h2(a[0], a[1]);
    o.y = pack_h2(a[2], a[3]);
    o.z = pack_h2(a[4], a[5]);
    o.w = pack_h2(a[6], a[7]);
    aggh4[(size_t)node * 8 + lane] = o;
}

// ---------------------------------------------------------------------------
// FP16 tensor-core fused MLP: h_out = relu(agg @ W1 + b1) @ W2 + b2
// mma.sync m16n8k16 f16.f16.f32. Block = 256 threads = 128 rows.
// W stored transposed [n][k]; GEMM2 A-frags == GEMM1 C-frags (same thread).
// mode 0: write hout (fp16); mode 1: fused global-max-pool into g_pool
// ---------------------------------------------------------------------------
__device__ __forceinline__ void mma_f16(float* c, uint32_t a0, uint32_t a1,
                                        uint32_t a2, uint32_t a3,
                                        uint32_t b0, uint32_t b1) {
    asm volatile(
        "mma.sync.aligned.m16n8k16.row.col.f32.f16.f16.f32 "
        "{%0,%1,%2,%3}, {%4,%5,%6,%7}, {%8,%9}, {%0,%1,%2,%3};"
        : "+f"(c[0]), "+f"(c[1]), "+f"(c[2]), "+f"(c[3])
        : "r"(a0), "r"(a1), "r"(a2), "r"(a3), "r"(b0), "r"(b1));
}

__global__ __launch_bounds__(256, 3) void mlp_tc_kernel(const uint4* __restrict__ xinh,
                                                        const __half* __restrict__ W1h,
                                                        const float* __restrict__ b1,
                                                        const __half* __restrict__ W2h,
                                                        const float* __restrict__ b2,
                                                        __half* __restrict__ hout,
                                                        const int* __restrict__ batch,
                                                        int mode) {
    __shared__ __half As[MROWS * SA];   // A tile (fp16)
    __shared__ __half Ws1[D * SA];      // W1^T (fp16)
    __shared__ __half Ws2[D * SA];      // W2^T (fp16)
    __shared__ float b1s[D];
    __shared__ float b2s[D];

    int tid = threadIdx.x;
    int warp = tid >> 5;
    int lane = tid & 31;
    int g = lane >> 2;   // group 0..7
    int th = lane & 3;   // thread-in-group 0..3
    int arow = warp * 16;
    int row0 = blockIdx.x * MROWS;

    // ---- stage A (128 rows x 8 uint4) + W1^T + W2^T ----
    for (int i = tid; i < MROWS * 8; i += 256) {
        int r = i >> 3;
        int c8 = (i & 7) << 3;
        uint4 t = make_uint4(0u, 0u, 0u, 0u);
        if (row0 + r < N_NODES)
            t = xinh[(size_t)(row0 + r) * 8 + (i & 7)];
        *reinterpret_cast<uint4*>(&As[r * SA + c8]) = t;
    }
    for (int i = tid; i < D * 8; i += 256) {
        int n = i >> 3;
        int c8 = (i & 7) << 3;
        uint4 t1 = reinterpret_cast<const uint4*>(W1h)[i];
        uint4 t2 = reinterpret_cast<const uint4*>(W2h)[i];
        *reinterpret_cast<uint4*>(&Ws1[n * SA + c8]) = t1;
        *reinterpret_cast<uint4*>(&Ws2[n * SA + c8]) = t2;
    }
    if (tid < D) { b1s[tid] = b1[tid]; b2s[tid] = b2[tid]; }
    __syncthreads();

    // ---- GEMM 1: acc = A @ W1  (4 k-chunks of 16) ----
    float acc[8][4];
#pragma unroll
    for (int n = 0; n < 8; n++)
#pragma unroll
        for (int j = 0; j < 4; j++) acc[n][j] = 0.f;

#pragma unroll
    for (int kc = 0; kc < 4; kc++) {
        uint32_t a0 = *reinterpret_cast<const uint32_t*>(&As[(arow + g) * SA + kc * 16 + 2 * th]);
        uint32_t a1 = *reinterpret_cast<const uint32_t*>(&As[(arow + g + 8) * SA + kc * 16 + 2 * th]);
        uint32_t a2 = *reinterpret_cast<const uint32_t*>(&As[(arow + g) * SA + kc * 16 + 2 * th + 8]);
        uint32_t a3 = *reinterpret_cast<const uint32_t*>(&As[(arow + g + 8) * SA + kc * 16 + 2 * th + 8]);
#pragma unroll
        for (int n = 0; n < 8; n++) {
            uint32_t bf0 = *reinterpret_cast<const uint32_t*>(&Ws1[(n * 8 + g) * SA + kc * 16 + 2 * th]);
            uint32_t bf1 = *reinterpret_cast<const uint32_t*>(&Ws1[(n * 8 + g) * SA + kc * 16 + 2 * th + 8]);
            mma_f16(acc[n], a0, a1, a2, a3, bf0, bf1);
        }
    }

    // ---- bias + relu (acc becomes T, fp32) ----
#pragma unroll
    for (int n = 0; n < 8; n++) {
        int c = n * 8 + 2 * th;
        acc[n][0] = fmaxf(acc[n][0] + b1s[c], 0.f);
        acc[n][1] = fmaxf(acc[n][1] + b1s[c + 1], 0.f);
        acc[n][2] = fmaxf(acc[n][2] + b1s[c], 0.f);
        acc[n][3] = fmaxf(acc[n][3] + b1s[c + 1], 0.f);
    }

    // ---- GEMM 2: acc2 = T @ W2; A-frags = own C-frags, cvt+pack only ----
    float acc2[8][4];
#pragma unroll
    for (int n = 0; n < 8; n++)
#pragma unroll
        for (int j = 0; j < 4; j++) acc2[n][j] = 0.f;

#pragma unroll
    for (int kc = 0; kc < 4; kc++) {
        uint32_t a0 = pack_h2(acc[2 * kc][0], acc[2 * kc][1]);
        uint32_t a1 = pack_h2(acc[2 * kc][2], acc[2 * kc][3]);
        uint32_t a2 = pack_h2(acc[2 * kc + 1][0], acc[2 * kc + 1][1]);
        uint32_t a3 = pack_h2(acc[2 * kc + 1][2], acc[2 * kc + 1][3]);
#pragma unroll
        for (int n = 0; n < 8; n++) {
            uint32_t bf0 = *reinterpret_cast<const uint32_t*>(&Ws2[(n * 8 + g) * SA + kc * 16 + 2 * th]);
            uint32_t bf1 = *reinterpret_cast<const uint32_t*>(&Ws2[(n * 8 + g) * SA + kc * 16 + 2 * th + 8]);
            mma_f16(acc2[n], a0, a1, a2, a3, bf0, bf1);
        }
    }

    // ---- bias + output ----
    int r0 = row0 + arow + g;
    int r1 = r0 + 8;
    bool v0 = (r0 < N_NODES);
    bool v1 = (r1 < N_NODES);

    if (mode == 0) {
#pragma unroll
        for (int n = 0; n < 8; n++) {
            int c = n * 8 + 2 * th;
            if (v0) {
                __half2 o = __floats2half2_rn(acc2[n][0] + b2s[c], acc2[n][1] + b2s[c + 1]);
                *reinterpret_cast<__half2*>(&hout[(size_t)r0 * D + c]) = o;
            }
            if (v1) {
                __half2 o = __floats2half2_rn(acc2[n][2] + b2s[c], acc2[n][3] + b2s[c + 1]);
                *reinterpret_cast<__half2*>(&hout[(size_t)r1 * D + c]) = o;
            }
        }
    } else {
        int gb0 = v0 ? batch[r0] : 0;
        int gb1 = v1 ? batch[r1] : 0;
        unsigned int* p0 = g_pool + (size_t)gb0 * D;
        unsigned int* p1 = g_pool + (size_t)gb1 * D;
#pragma unroll
        for (int n = 0; n < 8; n++) {
            int c = n * 8 + 2 * th;
#pragma unroll
            for (int j = 0; j < 4; j++) {
                float val = acc2[n][j] + b2s[c + (j & 1)];
                unsigned int bits = __float_as_uint(val);
                unsigned int enc = (bits & 0x80000000u) ? ~bits : (bits | 0x80000000u);
                if (j < 2) { if (v0) atomicMax(&p0[c + (j & 1)], enc); }
                else       { if (v1) atomicMax(&p1[c + (j & 1)], enc); }
            }
        }
    }
}

// ---------------------------------------------------------------------------
// FC head + log_softmax. One block (64 threads) per graph.
// ---------------------------------------------------------------------------
__global__ __launch_bounds__(64) void fc_kernel(const float* __restrict__ fcW1,
                                                const float* __restrict__ fcb1,
                                                const float* __restrict__ fcW2,
                                                const float* __restrict__ fcb2,
                                                float* __restrict__ out) {
    __shared__ float xr[D];
    __shared__ float hid[HID_FC];
    __shared__ float logits[N_CLASSES];
    __shared__ float m_s, lse_s;

    int g = blockIdx.x;
    int t = threadIdx.x;

    unsigned int e = g_pool[(size_t)g * D + t];
    unsigned int u = (e & 0x80000000u) ? (e & 0x7FFFFFFFu) : ~e;
    xr[t] = __uint_as_float(u);
    __syncthreads();

    float a = fcb1[t];
#pragma unroll
    for (int k = 0; k < D; k++) a += xr[k] * fcW1[k * HID_FC + t];
    hid[t] = fmaxf(a, 0.0f);
    __syncthreads();

    if (t < N_CLASSES) {
        float a2 = fcb2[t];
#pragma unroll
        for (int k = 0; k < HID_FC; k++) a2 += hid[k] * fcW2[k * N_CLASSES + t];
        logits[t] = a2;
    }
    __syncthreads();

    if (t == 0) {
        float m = logits[0];
#pragma unroll
        for (int j = 1; j < N_CLASSES; j++) m = fmaxf(m, logits[j]);
        float s = 0.0f;
#pragma unroll
        for (int j = 0; j < N_CLASSES; j++) s += expf(logits[j] - m);
        m_s = m;
        lse_s = logf(s);
    }
    __syncthreads();

    if (t < N_CLASSES) out[(size_t)g * N_CLASSES + t] = logits[t] - m_s - lse_s;
}

// ---------------------------------------------------------------------------
extern "C" void kernel_launch(void* const* d_in, const int* in_sizes, int n_in,
                              void* d_out, int out_size) {
    const float* x      = (const float*)d_in[0];
    const float* convW1 = (const float*)d_in[1];
    const float* convb1 = (const float*)d_in[2];
    const float* convW2 = (const float*)d_in[3];
    const float* convb2 = (const float*)d_in[4];
    const float* fcW1   = (const float*)d_in[5];
    const float* fcb1   = (const float*)d_in[6];
    const float* fcW2   = (const float*)d_in[7];
    const float* fcb2   = (const float*)d_in[8];
    const int* edge_index = (const int*)d_in[9];
    const int* batch      = (const int*)d_in[10];
    float* out = (float*)d_out;

    const int* src = edge_index;
    const int* dst = edge_index + N_EDGES;

    __half* xh_ptr = nullptr;
    __half* h_ptr = nullptr;
    __half* aggh_ptr = nullptr;
    int* cur_ptr = nullptr;
    __half* w1h_ptr = nullptr;
    __half* w2h_ptr = nullptr;
    cudaGetSymbolAddress((void**)&xh_ptr, g_xh);
    cudaGetSymbolAddress((void**)&h_ptr, g_h);
    cudaGetSymbolAddress((void**)&aggh_ptr, g_aggh);
    cudaGetSymbolAddress((void**)&cur_ptr, g_cur);
    cudaGetSymbolAddress((void**)&w1h_ptr, g_w1h);
    cudaGetSymbolAddress((void**)&w2h_ptr, g_w2h);

    const int gather_blocks = (N_NODES * 8 + 255) / 256;     // 1563
    const int mlp_blocks = (N_NODES + MROWS - 1) / MROWS;    // 391
    const int setup_blocks = (N_NODES * D / 2 + 255) / 256;  // covers all setup jobs

    // ---- per-replay setup ----
    cudaMemsetAsync(cur_ptr, 0, (size_t)N_NODES * sizeof(int));
    setup_kernel<<<setup_blocks, 256>>>(x, convW1, convW2, src, dst);

    // ---- 3 GIN layers ----
    for (int l = 0; l < N_LAYERS; l++) {
        const __half* hin = (l == 0) ? xh_ptr : h_ptr;
        int mode = (l == N_LAYERS - 1) ? 1 : 0;
        gather_kernel<<<gather_blocks, 256>>>((const uint4*)hin, (uint4*)aggh_ptr);
        mlp_tc_kernel<<<mlp_blocks, 256>>>((const uint4*)aggh_ptr,
                                           w1h_ptr + (size_t)l * D * D, convb1 + (size_t)l * D,
                                           w2h_ptr + (size_t)l * D * D, convb2 + (size_t)l * D,
                                           h_ptr, batch, mode);
    }

    fc_kernel<<<N_GRAPHS, 64>>>(fcW1, fcb1, fcW2, fcb2, out);
}

// round 16
// speedup vs baseline: 1.5535x; 1.0429x over previous
#include <cuda_runtime.h>
#include <cuda_fp16.h>
#include <cstdint>

#define N_NODES 50000
#define N_EDGES 800000
#define D 64
#define N_GRAPHS 512
#define N_LAYERS 3
#define HID_FC 64
#define N_CLASSES 10
#define SA 72      // smem stride in HALVES for A and W tiles: frag banks 4g+th
#define CAP 128    // adjacency bucket capacity per node (mean deg = 16)
#define MROWS 128  // rows per MLP block

// Scratch (device globals: no allocations allowed)
__device__ __half g_xh[N_NODES * D];     // input x, fp16
__device__ __half g_h[N_NODES * D];      // layer activations, fp16
__device__ __half g_aggh[N_NODES * D];   // aggregated rows, fp16
__device__ unsigned int g_pool[N_GRAPHS * D];
__device__ int g_cur[N_NODES];
__device__ unsigned int g_adj[N_NODES * CAP];  // stores src*8 (uint4-row offset)
__device__ __half g_w1h[N_LAYERS * D * D];  // W1 fp16, TRANSPOSED: [out n][in k]
__device__ __half g_w2h[N_LAYERS * D * D];  // W2 fp16, TRANSPOSED: [out n][in k]

// ---------------------------------------------------------------------------
__device__ __forceinline__ uint32_t pack_h2(float lo, float hi) {
    __half2 h = __floats2half2_rn(lo, hi);
    return *reinterpret_cast<uint32_t*>(&h);
}

__device__ __forceinline__ __half2 u2h2(uint32_t u) {
    return *reinterpret_cast<const __half2*>(&u);
}

// accumulate one fp16 row (uint4 = 8 halves) into fp32 accumulators
__device__ __forceinline__ void acc8(float* a, uint4 v) {
    float2 f;
    f = __half22float2(u2h2(v.x)); a[0] += f.x; a[1] += f.y;
    f = __half22float2(u2h2(v.y)); a[2] += f.x; a[3] += f.y;
    f = __half22float2(u2h2(v.z)); a[4] += f.x; a[5] += f.y;
    f = __half22float2(u2h2(v.w)); a[6] += f.x; a[7] += f.y;
}

// accumulate PAIR of fp16 rows: one HADD2 level, one cvt per pair
__device__ __forceinline__ void acc_pair(float* a, uint4 v0, uint4 v1) {
    float2 f;
    f = __half22float2(__hadd2(u2h2(v0.x), u2h2(v1.x))); a[0] += f.x; a[1] += f.y;
    f = __half22float2(__hadd2(u2h2(v0.y), u2h2(v1.y))); a[2] += f.x; a[3] += f.y;
    f = __half22float2(__hadd2(u2h2(v0.z), u2h2(v1.z))); a[4] += f.x; a[5] += f.y;
    f = __half22float2(__hadd2(u2h2(v0.w), u2h2(v1.w))); a[6] += f.x; a[7] += f.y;
}

// accumulate QUAD of fp16 rows: two HADD2 levels, one cvt per quad
__device__ __forceinline__ void acc_quad(float* a, uint4 v0, uint4 v1,
                                         uint4 v2, uint4 v3) {
    float2 f;
    f = __half22float2(__hadd2(__hadd2(u2h2(v0.x), u2h2(v1.x)),
                               __hadd2(u2h2(v2.x), u2h2(v3.x))));
    a[0] += f.x; a[1] += f.y;
    f = __half22float2(__hadd2(__hadd2(u2h2(v0.y), u2h2(v1.y)),
                               __hadd2(u2h2(v2.y), u2h2(v3.y))));
    a[2] += f.x; a[3] += f.y;
    f = __half22float2(__hadd2(__hadd2(u2h2(v0.z), u2h2(v1.z)),
                               __hadd2(u2h2(v2.z), u2h2(v3.z))));
    a[4] += f.x; a[5] += f.y;
    f = __half22float2(__hadd2(__hadd2(u2h2(v0.w), u2h2(v1.w)),
                               __hadd2(u2h2(v2.w), u2h2(v3.w))));
    a[6] += f.x; a[7] += f.y;
}

// ---------------------------------------------------------------------------
// Setup (once per replay): weights -> fp16 transposed, pool init, x -> fp16,
// adjacency fill with PRE-MULTIPLIED offsets (src*8 = uint4-row index).
// ---------------------------------------------------------------------------
__global__ void setup_kernel(const float* __restrict__ x,
                             const float* __restrict__ convW1,
                             const float* __restrict__ convW2,
                             const int* __restrict__ src,
                             const int* __restrict__ dst) {
    int i = blockIdx.x * blockDim.x + threadIdx.x;
    if (i < N_LAYERS * D * D) {
        int l = i >> 12;
        int rem = i & 4095;
        int n = rem >> 6;   // output col
        int k = rem & 63;   // input row
        g_w1h[i] = __float2half(convW1[(l << 12) + (k << 6) + n]);
        g_w2h[i] = __float2half(convW2[(l << 12) + (k << 6) + n]);
    }
    if (i < N_GRAPHS * D) g_pool[i] = 0x00800000u;  // encode(-FLT_MAX)
    if (i < N_NODES * D / 2) {
        float2 v = reinterpret_cast<const float2*>(x)[i];
        reinterpret_cast<__half2*>(g_xh)[i] = __floats2half2_rn(v.x, v.y);
    }
    if (i < N_EDGES / 8) {
        int e = i * 8;
        int4 d0 = *reinterpret_cast<const int4*>(dst + e);
        int4 d1 = *reinterpret_cast<const int4*>(dst + e + 4);
        int4 s0 = *reinterpret_cast<const int4*>(src + e);
        int4 s1 = *reinterpret_cast<const int4*>(src + e + 4);
        int p0 = atomicAdd(&g_cur[d0.x], 1);
        int p1 = atomicAdd(&g_cur[d0.y], 1);
        int p2 = atomicAdd(&g_cur[d0.z], 1);
        int p3 = atomicAdd(&g_cur[d0.w], 1);
        int p4 = atomicAdd(&g_cur[d1.x], 1);
        int p5 = atomicAdd(&g_cur[d1.y], 1);
        int p6 = atomicAdd(&g_cur[d1.z], 1);
        int p7 = atomicAdd(&g_cur[d1.w], 1);
        g_adj[d0.x * CAP + p0] = (unsigned int)s0.x * 8u;
        g_adj[d0.y * CAP + p1] = (unsigned int)s0.y * 8u;
        g_adj[d0.z * CAP + p2] = (unsigned int)s0.z * 8u;
        g_adj[d0.w * CAP + p3] = (unsigned int)s0.w * 8u;
        g_adj[d1.x * CAP + p4] = (unsigned int)s1.x * 8u;
        g_adj[d1.y * CAP + p5] = (unsigned int)s1.y * 8u;
        g_adj[d1.z * CAP + p6] = (unsigned int)s1.z * 8u;
        g_adj[d1.w * CAP + p7] = (unsigned int)s1.w * 8u;
    }
}

// ---------------------------------------------------------------------------
// Gather aggregation: aggh[n] = fp16(h[n] + sum_{j in N(n)} h[j]); h is fp16.
// 8 threads per node, one uint4 per lane. Index loads SOFTWARE-PIPELINED
// (next round's adj load issued before current rows are consumed);
// adjacency holds pre-multiplied uint4-row offsets (pure 32-bit adds).
// ---------------------------------------------------------------------------
__global__ __launch_bounds__(256, 6) void gather_kernel(const uint4* __restrict__ hin4,
                                                        uint4* __restrict__ aggh4) {
    unsigned int gid = blockIdx.x * 256u + threadIdx.x;
    unsigned int node = gid >> 3;
    unsigned int lane = gid & 7u;
    if (node >= N_NODES) return;
    unsigned int hm = 0xFFu << (threadIdx.x & 24);  // this 8-lane segment

    unsigned int self_off = node * 8u + lane;
    int cnt = g_cur[node];
    const unsigned int* adj = g_adj + node * CAP;

    // prologue: first idx batch in flight while the self row loads
    unsigned int idx = ((int)lane < cnt) ? __ldg(adj + lane) : 0u;

    float a[8];
    {
        uint4 s = hin4[self_off];  // self term (eps = 0)
        float2 f;
        f = __half22float2(u2h2(s.x)); a[0] = f.x; a[1] = f.y;
        f = __half22float2(u2h2(s.y)); a[2] = f.x; a[3] = f.y;
        f = __half22float2(u2h2(s.z)); a[4] = f.x; a[5] = f.y;
        f = __half22float2(u2h2(s.w)); a[6] = f.x; a[7] = f.y;
    }

    for (int base = 0; base < cnt; base += 8) {
        // pipeline: issue next round's idx load before consuming this round
        int nxt = base + 8 + (int)lane;
        unsigned int idx_next = (nxt < cnt) ? __ldg(adj + nxt) : 0u;

        int m = cnt - base;
        if (m >= 8) {
#pragma unroll
            for (int j = 0; j < 8; j += 4) {
                unsigned int o0 = __shfl_sync(hm, idx, j + 0, 8) + lane;
                unsigned int o1 = __shfl_sync(hm, idx, j + 1, 8) + lane;
                unsigned int o2 = __shfl_sync(hm, idx, j + 2, 8) + lane;
                unsigned int o3 = __shfl_sync(hm, idx, j + 3, 8) + lane;
                uint4 v0 = hin4[o0];
                uint4 v1 = hin4[o1];
                uint4 v2 = hin4[o2];
                uint4 v3 = hin4[o3];
                acc_quad(a, v0, v1, v2, v3);
            }
        } else {
            int j = 0;
            for (; j + 3 < m; j += 4) {
                unsigned int o0 = __shfl_sync(hm, idx, j + 0, 8) + lane;
                unsigned int o1 = __shfl_sync(hm, idx, j + 1, 8) + lane;
                unsigned int o2 = __shfl_sync(hm, idx, j + 2, 8) + lane;
                unsigned int o3 = __shfl_sync(hm, idx, j + 3, 8) + lane;
                acc_quad(a, hin4[o0], hin4[o1], hin4[o2], hin4[o3]);
            }
            for (; j + 1 < m; j += 2) {
                unsigned int oa = __shfl_sync(hm, idx, j, 8) + lane;
                unsigned int ob = __shfl_sync(hm, idx, j + 1, 8) + lane;
                acc_pair(a, hin4[oa], hin4[ob]);
            }
            if (j < m) {
                unsigned int ob = __shfl_sync(hm, idx, j, 8) + lane;
                acc8(a, hin4[ob]);
            }
        }
        idx = idx_next;
    }

    uint4 o;
    o.x = pack_h2(a[0], a[1]);
    o.y = pack_h2(a[2], a[3]);
    o.z = pack_h2(a[4], a[5]);
    o.w = pack_h2(a[6], a[7]);
    aggh4[self_off] = o;
}

// ---------------------------------------------------------------------------
// FP16 tensor-core fused MLP: h_out = relu(agg @ W1 + b1) @ W2 + b2
// mma.sync m16n8k16 f16.f16.f32. Block = 256 threads = 128 rows.
// W stored transposed [n][k]; GEMM2 A-frags == GEMM1 C-frags (same thread).
// mode 0: write hout (fp16); mode 1: fused global-max-pool into g_pool
// ---------------------------------------------------------------------------
__device__ __forceinline__ void mma_f16(float* c, uint32_t a0, uint32_t a1,
                                        uint32_t a2, uint32_t a3,
                                        uint32_t b0, uint32_t b1) {
    asm volatile(
        "mma.sync.aligned.m16n8k16.row.col.f32.f16.f16.f32 "
        "{%0,%1,%2,%3}, {%4,%5,%6,%7}, {%8,%9}, {%0,%1,%2,%3};"
        : "+f"(c[0]), "+f"(c[1]), "+f"(c[2]), "+f"(c[3])
        : "r"(a0), "r"(a1), "r"(a2), "r"(a3), "r"(b0), "r"(b1));
}

__global__ __launch_bounds__(256, 3) void mlp_tc_kernel(const uint4* __restrict__ xinh,
                                                        const __half* __restrict__ W1h,
                                                        const float* __restrict__ b1,
                                                        const __half* __restrict__ W2h,
                                                        const float* __restrict__ b2,
                                                        __half* __restrict__ hout,
                                                        const int* __restrict__ batch,
                                                        int mode) {
    __shared__ __half As[MROWS * SA];   // A tile (fp16)
    __shared__ __half Ws1[D * SA];      // W1^T (fp16)
    __shared__ __half Ws2[D * SA];      // W2^T (fp16)
    __shared__ float b1s[D];
    __shared__ float b2s[D];

    int tid = threadIdx.x;
    int warp = tid >> 5;
    int lane = tid & 31;
    int g = lane >> 2;   // group 0..7
    int th = lane & 3;   // thread-in-group 0..3
    int arow = warp * 16;
    int row0 = blockIdx.x * MROWS;

    // ---- stage A (128 rows x 8 uint4) + W1^T + W2^T ----
    for (int i = tid; i < MROWS * 8; i += 256) {
        int r = i >> 3;
        int c8 = (i & 7) << 3;
        uint4 t = make_uint4(0u, 0u, 0u, 0u);
        if (row0 + r < N_NODES)
            t = xinh[(size_t)(row0 + r) * 8 + (i & 7)];
        *reinterpret_cast<uint4*>(&As[r * SA + c8]) = t;
    }
    for (int i = tid; i < D * 8; i += 256) {
        int n = i >> 3;
        int c8 = (i & 7) << 3;
        uint4 t1 = reinterpret_cast<const uint4*>(W1h)[i];
        uint4 t2 = reinterpret_cast<const uint4*>(W2h)[i];
        *reinterpret_cast<uint4*>(&Ws1[n * SA + c8]) = t1;
        *reinterpret_cast<uint4*>(&Ws2[n * SA + c8]) = t2;
    }
    if (tid < D) { b1s[tid] = b1[tid]; b2s[tid] = b2[tid]; }
    __syncthreads();

    // ---- GEMM 1: acc = A @ W1  (4 k-chunks of 16) ----
    float acc[8][4];
#pragma unroll
    for (int n = 0; n < 8; n++)
#pragma unroll
        for (int j = 0; j < 4; j++) acc[n][j] = 0.f;

#pragma unroll
    for (int kc = 0; kc < 4; kc++) {
        uint32_t a0 = *reinterpret_cast<const uint32_t*>(&As[(arow + g) * SA + kc * 16 + 2 * th]);
        uint32_t a1 = *reinterpret_cast<const uint32_t*>(&As[(arow + g + 8) * SA + kc * 16 + 2 * th]);
        uint32_t a2 = *reinterpret_cast<const uint32_t*>(&As[(arow + g) * SA + kc * 16 + 2 * th + 8]);
        uint32_t a3 = *reinterpret_cast<const uint32_t*>(&As[(arow + g + 8) * SA + kc * 16 + 2 * th + 8]);
#pragma unroll
        for (int n = 0; n < 8; n++) {
            uint32_t bf0 = *reinterpret_cast<const uint32_t*>(&Ws1[(n * 8 + g) * SA + kc * 16 + 2 * th]);
            uint32_t bf1 = *reinterpret_cast<const uint32_t*>(&Ws1[(n * 8 + g) * SA + kc * 16 + 2 * th + 8]);
            mma_f16(acc[n], a0, a1, a2, a3, bf0, bf1);
        }
    }

    // ---- bias + relu (acc becomes T, fp32) ----
#pragma unroll
    for (int n = 0; n < 8; n++) {
        int c = n * 8 + 2 * th;
        acc[n][0] = fmaxf(acc[n][0] + b1s[c], 0.f);
        acc[n][1] = fmaxf(acc[n][1] + b1s[c + 1], 0.f);
        acc[n][2] = fmaxf(acc[n][2] + b1s[c], 0.f);
        acc[n][3] = fmaxf(acc[n][3] + b1s[c + 1], 0.f);
    }

    // ---- GEMM 2: acc2 = T @ W2; A-frags = own C-frags, cvt+pack only ----
    float acc2[8][4];
#pragma unroll
    for (int n = 0; n < 8; n++)
#pragma unroll
        for (int j = 0; j < 4; j++) acc2[n][j] = 0.f;

#pragma unroll
    for (int kc = 0; kc < 4; kc++) {
        uint32_t a0 = pack_h2(acc[2 * kc][0], acc[2 * kc][1]);
        uint32_t a1 = pack_h2(acc[2 * kc][2], acc[2 * kc][3]);
        uint32_t a2 = pack_h2(acc[2 * kc + 1][0], acc[2 * kc + 1][1]);
        uint32_t a3 = pack_h2(acc[2 * kc + 1][2], acc[2 * kc + 1][3]);
#pragma unroll
        for (int n = 0; n < 8; n++) {
            uint32_t bf0 = *reinterpret_cast<const uint32_t*>(&Ws2[(n * 8 + g) * SA + kc * 16 + 2 * th]);
            uint32_t bf1 = *reinterpret_cast<const uint32_t*>(&Ws2[(n * 8 + g) * SA + kc * 16 + 2 * th + 8]);
            mma_f16(acc2[n], a0, a1, a2, a3, bf0, bf1);
        }
    }

    // ---- bias + output ----
    int r0 = row0 + arow + g;
    int r1 = r0 + 8;
    bool v0 = (r0 < N_NODES);
    bool v1 = (r1 < N_NODES);

    if (mode == 0) {
#pragma unroll
        for (int n = 0; n < 8; n++) {
            int c = n * 8 + 2 * th;
            if (v0) {
                __half2 o = __floats2half2_rn(acc2[n][0] + b2s[c], acc2[n][1] + b2s[c + 1]);
                *reinterpret_cast<__half2*>(&hout[(size_t)r0 * D + c]) = o;
            }
            if (v1) {
                __half2 o = __floats2half2_rn(acc2[n][2] + b2s[c], acc2[n][3] + b2s[c + 1]);
                *reinterpret_cast<__half2*>(&hout[(size_t)r1 * D + c]) = o;
            }
        }
    } else {
        int gb0 = v0 ? batch[r0] : 0;
        int gb1 = v1 ? batch[r1] : 0;
        unsigned int* p0 = g_pool + (size_t)gb0 * D;
        unsigned int* p1 = g_pool + (size_t)gb1 * D;
#pragma unroll
        for (int n = 0; n < 8; n++) {
            int c = n * 8 + 2 * th;
#pragma unroll
            for (int j = 0; j < 4; j++) {
                float val = acc2[n][j] + b2s[c + (j & 1)];
                unsigned int bits = __float_as_uint(val);
                unsigned int enc = (bits & 0x80000000u) ? ~bits : (bits | 0x80000000u);
                if (j < 2) { if (v0) atomicMax(&p0[c + (j & 1)], enc); }
                else       { if (v1) atomicMax(&p1[c + (j & 1)], enc); }
            }
        }
    }
}

// ---------------------------------------------------------------------------
// FC head + log_softmax. One block (64 threads) per graph.
// ---------------------------------------------------------------------------
__global__ __launch_bounds__(64) void fc_kernel(const float* __restrict__ fcW1,
                                                const float* __restrict__ fcb1,
                                                const float* __restrict__ fcW2,
                                                const float* __restrict__ fcb2,
                                                float* __restrict__ out) {
    __shared__ float xr[D];
    __shared__ float hid[HID_FC];
    __shared__ float logits[N_CLASSES];
    __shared__ float m_s, lse_s;

    int g = blockIdx.x;
    int t = threadIdx.x;

    unsigned int e = g_pool[(size_t)g * D + t];
    unsigned int u = (e & 0x80000000u) ? (e & 0x7FFFFFFFu) : ~e;
    xr[t] = __uint_as_float(u);
    __syncthreads();

    float a = fcb1[t];
#pragma unroll
    for (int k = 0; k < D; k++) a += xr[k] * fcW1[k * HID_FC + t];
    hid[t] = fmaxf(a, 0.0f);
    __syncthreads();

    if (t < N_CLASSES) {
        float a2 = fcb2[t];
#pragma unroll
        for (int k = 0; k < HID_FC; k++) a2 += hid[k] * fcW2[k * N_CLASSES + t];
        logits[t] = a2;
    }
    __syncthreads();

    if (t == 0) {
        float m = logits[0];
#pragma unroll
        for (int j = 1; j < N_CLASSES; j++) m = fmaxf(m, logits[j]);
        float s = 0.0f;
#pragma unroll
        for (int j = 0; j < N_CLASSES; j++) s += expf(logits[j] - m);
        m_s = m;
        lse_s = logf(s);
    }
    __syncthreads();

    if (t < N_CLASSES) out[(size_t)g * N_CLASSES + t] = logits[t] - m_s - lse_s;
}

// ---------------------------------------------------------------------------
extern "C" void kernel_launch(void* const* d_in, const int* in_sizes, int n_in,
                              void* d_out, int out_size) {
    const float* x      = (const float*)d_in[0];
    const float* convW1 = (const float*)d_in[1];
    const float* convb1 = (const float*)d_in[2];
    const float* convW2 = (const float*)d_in[3];
    const float* convb2 = (const float*)d_in[4];
    const float* fcW1   = (const float*)d_in[5];
    const float* fcb1   = (const float*)d_in[6];
    const float* fcW2   = (const float*)d_in[7];
    const float* fcb2   = (const float*)d_in[8];
    const int* edge_index = (const int*)d_in[9];
    const int* batch      = (const int*)d_in[10];
    float* out = (float*)d_out;

    const int* src = edge_index;
    const int* dst = edge_index + N_EDGES;

    __half* xh_ptr = nullptr;
    __half* h_ptr = nullptr;
    __half* aggh_ptr = nullptr;
    int* cur_ptr = nullptr;
    __half* w1h_ptr = nullptr;
    __half* w2h_ptr = nullptr;
    cudaGetSymbolAddress((void**)&xh_ptr, g_xh);
    cudaGetSymbolAddress((void**)&h_ptr, g_h);
    cudaGetSymbolAddress((void**)&aggh_ptr, g_aggh);
    cudaGetSymbolAddress((void**)&cur_ptr, g_cur);
    cudaGetSymbolAddress((void**)&w1h_ptr, g_w1h);
    cudaGetSymbolAddress((void**)&w2h_ptr, g_w2h);

    const int gather_blocks = (N_NODES * 8 + 255) / 256;     // 1563
    const int mlp_blocks = (N_NODES + MROWS - 1) / MROWS;    // 391
    const int setup_blocks = (N_NODES * D / 2 + 255) / 256;  // covers all setup jobs

    // ---- per-replay setup ----
    cudaMemsetAsync(cur_ptr, 0, (size_t)N_NODES * sizeof(int));
    setup_kernel<<<setup_blocks, 256>>>(x, convW1, convW2, src, dst);

    // ---- 3 GIN layers ----
    for (int l = 0; l < N_LAYERS; l++) {
        const __half* hin = (l == 0) ? xh_ptr : h_ptr;
        int mode = (l == N_LAYERS - 1) ? 1 : 0;
        gather_kernel<<<gather_blocks, 256>>>((const uint4*)hin, (uint4*)aggh_ptr);
        mlp_tc_kernel<<<mlp_blocks, 256>>>((const uint4*)aggh_ptr,
                                           w1h_ptr + (size_t)l * D * D, convb1 + (size_t)l * D,
                                           w2h_ptr + (size_t)l * D * D, convb2 + (size_t)l * D,
                                           h_ptr, batch, mode);
    }

    fc_kernel<<<N_GRAPHS, 64>>>(fcW1, fcb1, fcW2, fcb2, out);
}